// round 2
// baseline (speedup 1.0000x reference)
#include <cuda_runtime.h>
#include <cstdint>

// Problem dims
#define BB   16384
#define DOBS 512
#define NE   8
#define NA   32
#define G1   256
#define G2   128
#define E1   1024
#define E2   512
#define E3   256
#define NP   (2*BB)   // total (token, expert) pairs = 32768

typedef unsigned long long u64;

// ---------------- scratch (static device allocations) ----------------
__device__ float g_g1[BB*G1];
__device__ float g_g2[BB*G2];
__device__ int   g_tidx[BB*2];
__device__ float g_tw[BB*2];
__device__ int   g_counts[NE];
__device__ int   g_off[NE+1];
__device__ int   g_tile128[NE+1];
__device__ int   g_tile32[NE+1];
__device__ int   g_cursor[NE];
__device__ int   g_tok[NP];
__device__ float g_wt[NP];
__device__ float g_h1[(size_t)NP*E1];
__device__ float g_h2[(size_t)NP*E2];
__device__ float g_h3[(size_t)NP*E3];

__device__ __forceinline__ float eluf(float x) { return x > 0.f ? x : expm1f(x); }

__device__ __forceinline__ u64 pack2(float x, float y) {
    u64 r; asm("mov.b64 %0, {%1, %2};" : "=l"(r) : "f"(x), "f"(y)); return r;
}
__device__ __forceinline__ u64 fma2(u64 a, u64 b, u64 c) {
    u64 d; asm("fma.rn.f32x2 %0, %1, %2, %3;" : "=l"(d) : "l"(a), "l"(b), "l"(c)); return d;
}
__device__ __forceinline__ float2 unpack2(u64 v) {
    float2 f; asm("mov.b64 {%0, %1}, %2;" : "=f"(f.x), "=f"(f.y) : "l"(v)); return f;
}

// ---------------- init: zero counters ----------------
__global__ void init_kernel() {
    int t = threadIdx.x;
    if (t < NE) { g_counts[t] = 0; g_cursor[t] = 0; }
}

// ---------------- tiled SGEMM with packed f32x2 FMA ----------------
// BM=BN=128, BK=16, 256 threads, 8x8 per-thread microtile held as 8x4 f32x2.
// A is stored DUPLICATED in shared ([a,a] pairs) so the inner loop needs no packing.
// GROUPED: rows partitioned per-expert via g_off/g_tile128; W/bias per expert.
// GATHER:  A row index comes from g_tok[] (layer-1 reads obs rows).
template<bool GROUPED, bool GATHER, bool ELU>
__global__ __launch_bounds__(256, 2)
void sgemm_kernel(const float* __restrict__ A, const float* __restrict__ W,
                  const float* __restrict__ bias, float* __restrict__ C,
                  int M, int K, int N)
{
    int row0, rowEnd;
    if (GROUPED) {
        int bx = blockIdx.x;
        if (bx >= g_tile128[NE]) return;
        int e = 0;
        while (bx >= g_tile128[e+1]) e++;
        row0   = g_off[e] + (bx - g_tile128[e]) * 128;
        rowEnd = g_off[e+1];
        if (row0 >= rowEnd) return;
        W    += (size_t)e * K * N;
        bias += e * N;
    } else {
        row0   = blockIdx.x * 128;
        rowEnd = M;
    }
    const int n0 = blockIdx.y * 128;

    __shared__ float As2[16][256];   // duplicated A: [k][2*row+{0,1}]
    __shared__ float Bs[16][128];

    const int tid  = threadIdx.x;
    const int aRow = tid >> 1, aCol = (tid & 1) * 4;
    const int bRow = tid >> 5, bCol = (tid & 31) * 4;
    const int tx   = tid & 15, ty   = tid >> 4;

    u64 acc2[8][4];
#pragma unroll
    for (int i = 0; i < 8; i++)
#pragma unroll
        for (int q = 0; q < 4; q++) acc2[i][q] = 0ull;

    const int grow = row0 + aRow;
    const bool avalid = grow < rowEnd;
    const float* arow_ptr = nullptr;
    if (avalid) {
        if (GATHER) arow_ptr = A + (size_t)g_tok[grow] * K;
        else        arow_ptr = A + (size_t)grow * K;
    }

    for (int k0 = 0; k0 < K; k0 += 16) {
        float4 av0 = make_float4(0.f,0.f,0.f,0.f);
        float4 av1 = make_float4(0.f,0.f,0.f,0.f);
        if (avalid) {
            av0 = *(const float4*)(arow_ptr + k0 + aCol);
            av1 = *(const float4*)(arow_ptr + k0 + 8 + aCol);
        }
        float4 bv0 = *(const float4*)(W + (size_t)(k0 + bRow) * N + n0 + bCol);
        float4 bv1 = *(const float4*)(W + (size_t)(k0 + 8 + bRow) * N + n0 + bCol);
        __syncthreads();
        // duplicated A stores (STS.64 each)
        *(u64*)&As2[aCol+0][2*aRow] = pack2(av0.x, av0.x);
        *(u64*)&As2[aCol+1][2*aRow] = pack2(av0.y, av0.y);
        *(u64*)&As2[aCol+2][2*aRow] = pack2(av0.z, av0.z);
        *(u64*)&As2[aCol+3][2*aRow] = pack2(av0.w, av0.w);
        *(u64*)&As2[aCol+8][2*aRow] = pack2(av1.x, av1.x);
        *(u64*)&As2[aCol+9][2*aRow] = pack2(av1.y, av1.y);
        *(u64*)&As2[aCol+10][2*aRow] = pack2(av1.z, av1.z);
        *(u64*)&As2[aCol+11][2*aRow] = pack2(av1.w, av1.w);
        *(float4*)&Bs[bRow][bCol]   = bv0;
        *(float4*)&Bs[bRow+8][bCol] = bv1;
        __syncthreads();
#pragma unroll
        for (int kk = 0; kk < 16; kk++) {
            const ulonglong2* ap = (const ulonglong2*)&As2[kk][ty*16];
            const ulonglong2* bp = (const ulonglong2*)&Bs[kk][tx*8];
            ulonglong2 bq0 = bp[0], bq1 = bp[1];
#pragma unroll
            for (int i2 = 0; i2 < 4; i2++) {
                ulonglong2 aa = ap[i2];
                acc2[2*i2+0][0] = fma2(aa.x, bq0.x, acc2[2*i2+0][0]);
                acc2[2*i2+0][1] = fma2(aa.x, bq0.y, acc2[2*i2+0][1]);
                acc2[2*i2+0][2] = fma2(aa.x, bq1.x, acc2[2*i2+0][2]);
                acc2[2*i2+0][3] = fma2(aa.x, bq1.y, acc2[2*i2+0][3]);
                acc2[2*i2+1][0] = fma2(aa.y, bq0.x, acc2[2*i2+1][0]);
                acc2[2*i2+1][1] = fma2(aa.y, bq0.y, acc2[2*i2+1][1]);
                acc2[2*i2+1][2] = fma2(aa.y, bq1.x, acc2[2*i2+1][2]);
                acc2[2*i2+1][3] = fma2(aa.y, bq1.y, acc2[2*i2+1][3]);
            }
        }
    }

#pragma unroll
    for (int i = 0; i < 8; i++) {
        int r = row0 + ty*8 + i;
        if (r < rowEnd) {
            const int c = n0 + tx*8;
            float2 v0 = unpack2(acc2[i][0]);
            float2 v1 = unpack2(acc2[i][1]);
            float2 v2 = unpack2(acc2[i][2]);
            float2 v3 = unpack2(acc2[i][3]);
            float4 o0, o1;
            o0.x = v0.x + bias[c+0]; o0.y = v0.y + bias[c+1];
            o0.z = v1.x + bias[c+2]; o0.w = v1.y + bias[c+3];
            o1.x = v2.x + bias[c+4]; o1.y = v2.y + bias[c+5];
            o1.z = v3.x + bias[c+6]; o1.w = v3.y + bias[c+7];
            if (ELU) {
                o0.x = eluf(o0.x); o0.y = eluf(o0.y); o0.z = eluf(o0.z); o0.w = eluf(o0.w);
                o1.x = eluf(o1.x); o1.y = eluf(o1.y); o1.z = eluf(o1.z); o1.w = eluf(o1.w);
            }
            *(float4*)(C + (size_t)r * N + c)     = o0;
            *(float4*)(C + (size_t)r * N + c + 4) = o1;
        }
    }
}

// ---------------- gating head: logits + top-2 + renorm + counts ----------------
__global__ __launch_bounds__(128)
void gate_topk_kernel(const float* __restrict__ gw3, const float* __restrict__ gb3)
{
    __shared__ float sG[64*129];
    __shared__ float sW[G2*NE];
    __shared__ float sB[NE];
    const int tid = threadIdx.x;
    const int b0  = blockIdx.x * 64;
    for (int i = tid; i < 64*G2; i += 128)
        sG[(i >> 7)*129 + (i & 127)] = g_g2[(size_t)b0*G2 + i];
    for (int i = tid; i < G2*NE; i += 128) sW[i] = gw3[i];
    if (tid < NE) sB[tid] = gb3[tid];
    __syncthreads();
    if (tid < 64) {
        float lg[NE];
#pragma unroll
        for (int j = 0; j < NE; j++) lg[j] = sB[j];
        for (int k = 0; k < G2; k++) {
            float gv = sG[tid*129 + k];
#pragma unroll
            for (int j = 0; j < NE; j++) lg[j] += gv * sW[k*NE + j];
        }
        int i0 = 0; float m0 = lg[0];
#pragma unroll
        for (int j = 1; j < NE; j++) if (lg[j] > m0) { m0 = lg[j]; i0 = j; }
        int i1 = -1; float m1 = -3.4e38f;
#pragma unroll
        for (int j = 0; j < NE; j++) if (j != i0 && lg[j] > m1) { m1 = lg[j]; i1 = j; }
        float e1  = expf(m1 - m0);
        float inv = 1.f / (1.f + e1);
        int b = b0 + tid;
        g_tidx[b*2+0] = i0; g_tidx[b*2+1] = i1;
        g_tw[b*2+0] = inv;  g_tw[b*2+1] = e1 * inv;
        atomicAdd(&g_counts[i0], 1);
        atomicAdd(&g_counts[i1], 1);
    }
}

// ---------------- prefix sums ----------------
__global__ void offsets_kernel()
{
    if (threadIdx.x == 0 && blockIdx.x == 0) {
        int o = 0, t128 = 0, t32 = 0;
        for (int e = 0; e < NE; e++) {
            g_off[e] = o; g_tile128[e] = t128; g_tile32[e] = t32;
            int c = g_counts[e];
            o += c; t128 += (c + 127) >> 7; t32 += (c + 31) >> 5;
        }
        g_off[NE] = o; g_tile128[NE] = t128; g_tile32[NE] = t32;
    }
}

// ---------------- scatter tokens into per-expert slot lists ----------------
__global__ __launch_bounds__(256)
void scatter_kernel()
{
    const int b    = blockIdx.x * 256 + threadIdx.x;
    const int lane = threadIdx.x & 31;
#pragma unroll
    for (int s = 0; s < 2; s++) {
        int   e = g_tidx[b*2 + s];
        float w = g_tw[b*2 + s];
#pragma unroll
        for (int ee = 0; ee < NE; ee++) {
            unsigned m = __ballot_sync(0xffffffffu, e == ee);
            if (e == ee) {
                int rank   = __popc(m & ((1u << lane) - 1u));
                int leader = __ffs(m) - 1;
                int base = 0;
                if (lane == leader) base = atomicAdd(&g_cursor[ee], __popc(m));
                base = __shfl_sync(m, base, leader);
                int p = g_off[ee] + base + rank;
                g_tok[p] = b; g_wt[p] = w;
            }
        }
    }
}

// ---------------- layer 4 (K=256, N=32) fused with weighted combine ----------------
__global__ __launch_bounds__(256)
void l4_combine_kernel(const float* __restrict__ H3, const float* __restrict__ W4,
                       const float* __restrict__ B4, float* __restrict__ out)
{
    const int bx = blockIdx.x;
    if (bx >= g_tile32[NE]) return;
    int e = 0;
    while (bx >= g_tile32[e+1]) e++;
    const int row0   = g_off[e] + (bx - g_tile32[e]) * 32;
    const int rowEnd = g_off[e+1];

    __shared__ float sW[E3*NA];   // 32 KB
    const float* We = W4 + (size_t)e * E3 * NA;
    for (int i = threadIdx.x; i < E3*NA/4; i += 256)
        *(float4*)&sW[i*4] = *(const float4*)&We[i*4];
    __syncthreads();

    const int r  = threadIdx.x >> 3;
    const int c4 = (threadIdx.x & 7) * 4;
    const int row = row0 + r;
    if (row >= rowEnd) return;

    const float* h = H3 + (size_t)row * E3;
    float a0 = 0.f, a1 = 0.f, a2 = 0.f, a3 = 0.f;
#pragma unroll 4
    for (int k = 0; k < E3; k += 4) {
        float4 hv = *(const float4*)&h[k];
        float4 w0 = *(float4*)&sW[(k+0)*NA + c4];
        float4 w1 = *(float4*)&sW[(k+1)*NA + c4];
        float4 w2 = *(float4*)&sW[(k+2)*NA + c4];
        float4 w3 = *(float4*)&sW[(k+3)*NA + c4];
        a0 += hv.x*w0.x + hv.y*w1.x + hv.z*w2.x + hv.w*w3.x;
        a1 += hv.x*w0.y + hv.y*w1.y + hv.z*w2.y + hv.w*w3.y;
        a2 += hv.x*w0.z + hv.y*w1.z + hv.z*w2.z + hv.w*w3.z;
        a3 += hv.x*w0.w + hv.y*w1.w + hv.z*w2.w + hv.w*w3.w;
    }
    const int   tok = g_tok[row];
    const float w   = g_wt[row];
    float* o = out + (size_t)tok * NA + c4;
    atomicAdd(o+0, w*(a0 + B4[e*NA + c4 + 0]));
    atomicAdd(o+1, w*(a1 + B4[e*NA + c4 + 1]));
    atomicAdd(o+2, w*(a2 + B4[e*NA + c4 + 2]));
    atomicAdd(o+3, w*(a3 + B4[e*NA + c4 + 3]));
}

// ---------------- launch ----------------
extern "C" void kernel_launch(void* const* d_in, const int* in_sizes, int n_in,
                              void* d_out, int out_size)
{
    const float* obs = (const float*)d_in[0];
    const float* gw1 = (const float*)d_in[1];
    const float* gb1 = (const float*)d_in[2];
    const float* gw2 = (const float*)d_in[3];
    const float* gb2 = (const float*)d_in[4];
    const float* gw3 = (const float*)d_in[5];
    const float* gb3 = (const float*)d_in[6];
    const float* ew1 = (const float*)d_in[7];
    const float* eb1 = (const float*)d_in[8];
    const float* ew2 = (const float*)d_in[9];
    const float* eb2 = (const float*)d_in[10];
    const float* ew3 = (const float*)d_in[11];
    const float* eb3 = (const float*)d_in[12];
    const float* ew4 = (const float*)d_in[13];
    const float* eb4 = (const float*)d_in[14];
    float* out = (float*)d_out;

    float *pg1, *pg2, *ph1, *ph2, *ph3;
    cudaGetSymbolAddress((void**)&pg1, g_g1);
    cudaGetSymbolAddress((void**)&pg2, g_g2);
    cudaGetSymbolAddress((void**)&ph1, g_h1);
    cudaGetSymbolAddress((void**)&ph2, g_h2);
    cudaGetSymbolAddress((void**)&ph3, g_h3);

    init_kernel<<<1, 32>>>();
    cudaMemsetAsync(out, 0, (size_t)out_size * sizeof(float));

    // gating MLP
    sgemm_kernel<false,false,true><<<dim3(BB/128, G1/128), 256>>>(obs, gw1, gb1, pg1, BB, DOBS, G1);
    sgemm_kernel<false,false,true><<<dim3(BB/128, G2/128), 256>>>(pg1, gw2, gb2, pg2, BB, G1, G2);
    gate_topk_kernel<<<BB/64, 128>>>(gw3, gb3);
    offsets_kernel<<<1, 32>>>();
    scatter_kernel<<<BB/256, 256>>>();

    // grouped expert layers (upper-bound grids; extra blocks exit early)
    const int T128 = NP/128 + NE;   // 264
    const int T32  = NP/32  + NE;   // 1032
    sgemm_kernel<true,true ,true><<<dim3(T128, E1/128), 256>>>(obs, ew1, eb1, ph1, 0, DOBS, E1);
    sgemm_kernel<true,false,true><<<dim3(T128, E2/128), 256>>>(ph1, ew2, eb2, ph2, 0, E1, E2);
    sgemm_kernel<true,false,true><<<dim3(T128, E3/128), 256>>>(ph2, ew3, eb3, ph3, 0, E2, E3);

    // layer 4 + weighted combine
    l4_combine_kernel<<<T32, 256>>>(ph3, ew4, eb4, out);
}

// round 3
// speedup vs baseline: 1.8239x; 1.8239x over previous
#include <cuda_runtime.h>
#include <cuda_bf16.h>
#include <cstdint>

// Problem dims
#define BB   16384
#define DOBS 512
#define NE   8
#define NA   32
#define G1   256
#define G2   128
#define E1   1024
#define E2   512
#define E3   256
#define NP   (2*BB)   // total (token, expert) pairs = 32768

typedef __nv_bfloat16 bf16;
typedef __nv_bfloat162 bf162;

// ---------------- scratch (static device allocations) ----------------
__device__ __align__(16) bf16 g_obs_h[BB*DOBS];
__device__ __align__(16) bf16 g_obs_l[BB*DOBS];
__device__ __align__(16) bf16 g_gw1h[DOBS*G1], g_gw1l[DOBS*G1];
__device__ __align__(16) bf16 g_gw2h[G1*G2],   g_gw2l[G1*G2];
__device__ __align__(16) bf16 g_ew1h[NE*DOBS*E1], g_ew1l[NE*DOBS*E1];
__device__ __align__(16) bf16 g_ew2h[NE*E1*E2],   g_ew2l[NE*E1*E2];
__device__ __align__(16) bf16 g_ew3h[NE*E2*E3],   g_ew3l[NE*E2*E3];

__device__ __align__(16) bf16 g_g1h[BB*G1], g_g1l[BB*G1];
__device__ __align__(16) float g_g2[BB*G2];
__device__ __align__(16) bf16 g_h1h[(size_t)NP*E1], g_h1l[(size_t)NP*E1];
__device__ __align__(16) bf16 g_h2h[(size_t)NP*E2], g_h2l[(size_t)NP*E2];
__device__ __align__(16) bf16 g_h3h[(size_t)NP*E3], g_h3l[(size_t)NP*E3];

__device__ int   g_tidx[BB*2];
__device__ float g_tw[BB*2];
__device__ int   g_counts[NE];
__device__ int   g_off[NE+1];
__device__ int   g_tile128[NE+1];
__device__ int   g_tile32[NE+1];
__device__ int   g_cursor[NE];
__device__ int   g_tok[NP];
__device__ float g_wt[NP];

__device__ __forceinline__ float eluf(float x) { return x > 0.f ? x : expm1f(x); }

// ---------------- mma / ldmatrix helpers ----------------
__device__ __forceinline__ void mma_bf16(float* c, const unsigned* a, const unsigned* b) {
    asm volatile(
        "mma.sync.aligned.m16n8k16.row.col.f32.bf16.bf16.f32 "
        "{%0,%1,%2,%3}, {%4,%5,%6,%7}, {%8,%9}, {%0,%1,%2,%3};"
        : "+f"(c[0]), "+f"(c[1]), "+f"(c[2]), "+f"(c[3])
        : "r"(a[0]), "r"(a[1]), "r"(a[2]), "r"(a[3]), "r"(b[0]), "r"(b[1]));
}
__device__ __forceinline__ void ldsm_x4(unsigned* r, unsigned addr) {
    asm volatile("ldmatrix.sync.aligned.m8n8.x4.shared.b16 {%0,%1,%2,%3}, [%4];"
                 : "=r"(r[0]), "=r"(r[1]), "=r"(r[2]), "=r"(r[3]) : "r"(addr));
}
__device__ __forceinline__ void ldsm_x4_t(unsigned* r, unsigned addr) {
    asm volatile("ldmatrix.sync.aligned.m8n8.x4.trans.shared.b16 {%0,%1,%2,%3}, [%4];"
                 : "=r"(r[0]), "=r"(r[1]), "=r"(r[2]), "=r"(r[3]) : "r"(addr));
}

// ---------------- split fp32 -> (hi, lo) bf16 ----------------
__global__ __launch_bounds__(256)
void split_kernel(const float4* __restrict__ x, bf162* __restrict__ hi,
                  bf162* __restrict__ lo, int n4)
{
    int i = blockIdx.x * 256 + threadIdx.x;
    if (i >= n4) return;
    float4 v = x[i];
    bf16 h0 = __float2bfloat16_rn(v.x);
    bf16 h1 = __float2bfloat16_rn(v.y);
    bf16 h2 = __float2bfloat16_rn(v.z);
    bf16 h3 = __float2bfloat16_rn(v.w);
    bf16 l0 = __float2bfloat16_rn(v.x - __bfloat162float(h0));
    bf16 l1 = __float2bfloat16_rn(v.y - __bfloat162float(h1));
    bf16 l2 = __float2bfloat16_rn(v.z - __bfloat162float(h2));
    bf16 l3 = __float2bfloat16_rn(v.w - __bfloat162float(h3));
    hi[2*i]   = bf162(h0, h1);
    hi[2*i+1] = bf162(h2, h3);
    lo[2*i]   = bf162(l0, l1);
    lo[2*i+1] = bf162(l2, l3);
}

// ---------------- init ----------------
__global__ void init_kernel() {
    int t = threadIdx.x;
    if (t < NE) { g_counts[t] = 0; g_cursor[t] = 0; }
}

// ---------------- tensor-core grouped GEMM (split-bf16, 3-pass) ----------------
// C = ELU(A @ W + bias) with A ~ Ah+Al, W ~ Wh+Wl; acc = Ah*Wh + Ah*Wl + Al*Wh.
// CTA tile 128x128, BK=32, 256 threads (8 warps, warp tile 32x64).
// OUTSPLIT: write (Ch, Cl) bf16 pair; else write fp32 Cf.
template<bool GROUPED, bool GATHER, bool OUTSPLIT>
__global__ __launch_bounds__(256)
void mma_gemm(const bf16* __restrict__ Ah, const bf16* __restrict__ Al,
              const bf16* __restrict__ Wh, const bf16* __restrict__ Wl,
              const float* __restrict__ bias,
              bf16* __restrict__ Ch, bf16* __restrict__ Cl, float* __restrict__ Cf,
              int M, int K, int N)
{
    int row0, rowEnd;
    if (GROUPED) {
        int bx = blockIdx.x;
        if (bx >= g_tile128[NE]) return;
        int e = 0;
        while (bx >= g_tile128[e+1]) e++;
        row0   = g_off[e] + (bx - g_tile128[e]) * 128;
        rowEnd = g_off[e+1];
        if (row0 >= rowEnd) return;
        Wh   += (size_t)e * K * N;
        Wl   += (size_t)e * K * N;
        bias += e * N;
    } else {
        row0   = blockIdx.x * 128;
        rowEnd = M;
    }
    const int n0 = blockIdx.y * 128;

    __shared__ __align__(16) bf16 sAh[128*40];
    __shared__ __align__(16) bf16 sAl[128*40];
    __shared__ __align__(16) bf16 sBh[32*136];
    __shared__ __align__(16) bf16 sBl[32*136];

    const int tid  = threadIdx.x;
    const int lane = tid & 31;
    const int wid  = tid >> 5;
    const int warpM = wid & 3;     // 4 warps over M (32 rows each)
    const int warpN = wid >> 2;    // 2 warps over N (64 cols each)

    // --- A load mapping: 2 rows/thread, 8 bf16 (16B) each ---
    const int ar = tid >> 2;          // 0..63
    const int ak = (tid & 3) * 8;     // 0,8,16,24
    bool av[2]; const bf16 *pAh[2], *pAl[2];
#pragma unroll
    for (int i = 0; i < 2; i++) {
        int gr = row0 + ar + 64*i;
        av[i] = gr < rowEnd;
        long rowIdx = 0;
        if (av[i]) rowIdx = GATHER ? (long)g_tok[gr] : (long)gr;
        pAh[i] = Ah + (size_t)rowIdx * K + ak;
        pAl[i] = Al + (size_t)rowIdx * K + ak;
    }
    // --- B load mapping: 2 rows/thread of 8 bf16 ---
    const int bk = tid >> 4;          // 0..15
    const int bn = (tid & 15) * 8;    // 0..120

    float acc[2][8][4];
#pragma unroll
    for (int mt = 0; mt < 2; mt++)
#pragma unroll
        for (int nt = 0; nt < 8; nt++)
#pragma unroll
            for (int q = 0; q < 4; q++) acc[mt][nt][q] = 0.f;

    const unsigned uAh = (unsigned)__cvta_generic_to_shared(sAh);
    const unsigned uAl = (unsigned)__cvta_generic_to_shared(sAl);
    const unsigned uBh = (unsigned)__cvta_generic_to_shared(sBh);
    const unsigned uBl = (unsigned)__cvta_generic_to_shared(sBl);

    const uint4 zero4 = make_uint4(0,0,0,0);

    for (int k0 = 0; k0 < K; k0 += 32) {
        __syncthreads();
#pragma unroll
        for (int i = 0; i < 2; i++) {
            int r = ar + 64*i;
            uint4 vh = av[i] ? *(const uint4*)(pAh[i] + k0) : zero4;
            uint4 vl = av[i] ? *(const uint4*)(pAl[i] + k0) : zero4;
            *(uint4*)&sAh[r*40 + ak] = vh;
            *(uint4*)&sAl[r*40 + ak] = vl;
        }
#pragma unroll
        for (int i = 0; i < 2; i++) {
            int k = bk + 16*i;
            const bf16* ph = Wh + (size_t)(k0 + k) * N + n0 + bn;
            const bf16* pl = Wl + (size_t)(k0 + k) * N + n0 + bn;
            *(uint4*)&sBh[k*136 + bn] = *(const uint4*)ph;
            *(uint4*)&sBl[k*136 + bn] = *(const uint4*)pl;
        }
        __syncthreads();

#pragma unroll
        for (int kk = 0; kk < 32; kk += 16) {
            unsigned ah[2][4], al[2][4];
            const int arow = warpM*32 + (lane & 15);
            const int acol = kk + 8*(lane >> 4);
#pragma unroll
            for (int mt = 0; mt < 2; mt++) {
                unsigned off = (unsigned)(((arow + mt*16)*40 + acol) * 2);
                ldsm_x4(ah[mt], uAh + off);
                ldsm_x4(al[mt], uAl + off);
            }
            const int brow = kk + (lane & 15);
#pragma unroll
            for (int np = 0; np < 4; np++) {
                const int bcol = warpN*64 + np*16 + 8*(lane >> 4);
                unsigned off = (unsigned)((brow*136 + bcol) * 2);
                unsigned bh[4], bl[4];
                ldsm_x4_t(bh, uBh + off);
                ldsm_x4_t(bl, uBl + off);
#pragma unroll
                for (int mt = 0; mt < 2; mt++) {
                    mma_bf16(acc[mt][2*np],   ah[mt], bh);
                    mma_bf16(acc[mt][2*np+1], ah[mt], bh+2);
                    mma_bf16(acc[mt][2*np],   ah[mt], bl);
                    mma_bf16(acc[mt][2*np+1], ah[mt], bl+2);
                    mma_bf16(acc[mt][2*np],   al[mt], bh);
                    mma_bf16(acc[mt][2*np+1], al[mt], bh+2);
                }
            }
        }
    }

    // ---------------- epilogue ----------------
#pragma unroll
    for (int mt = 0; mt < 2; mt++) {
        int r0 = row0 + warpM*32 + mt*16 + (lane >> 2);
#pragma unroll
        for (int nt = 0; nt < 8; nt++) {
            int c = n0 + warpN*64 + nt*8 + 2*(lane & 3);
            float b0 = __ldg(bias + c), b1 = __ldg(bias + c + 1);
            float v00 = eluf(acc[mt][nt][0] + b0);
            float v01 = eluf(acc[mt][nt][1] + b1);
            float v10 = eluf(acc[mt][nt][2] + b0);
            float v11 = eluf(acc[mt][nt][3] + b1);
            if (r0 < rowEnd) {
                if (OUTSPLIT) {
                    bf16 h0 = __float2bfloat16_rn(v00);
                    bf16 h1 = __float2bfloat16_rn(v01);
                    *(bf162*)(Ch + (size_t)r0*N + c) = bf162(h0, h1);
                    *(bf162*)(Cl + (size_t)r0*N + c) =
                        bf162(__float2bfloat16_rn(v00 - __bfloat162float(h0)),
                              __float2bfloat16_rn(v01 - __bfloat162float(h1)));
                } else {
                    *(float2*)(Cf + (size_t)r0*N + c) = make_float2(v00, v01);
                }
            }
            if (r0 + 8 < rowEnd) {
                if (OUTSPLIT) {
                    bf16 h0 = __float2bfloat16_rn(v10);
                    bf16 h1 = __float2bfloat16_rn(v11);
                    *(bf162*)(Ch + (size_t)(r0+8)*N + c) = bf162(h0, h1);
                    *(bf162*)(Cl + (size_t)(r0+8)*N + c) =
                        bf162(__float2bfloat16_rn(v10 - __bfloat162float(h0)),
                              __float2bfloat16_rn(v11 - __bfloat162float(h1)));
                } else {
                    *(float2*)(Cf + (size_t)(r0+8)*N + c) = make_float2(v10, v11);
                }
            }
        }
    }
}

// ---------------- gating head: logits + top-2 + renorm + counts ----------------
__global__ __launch_bounds__(128)
void gate_topk_kernel(const float* __restrict__ gw3, const float* __restrict__ gb3)
{
    __shared__ float sG[64*129];
    __shared__ float sW[G2*NE];
    __shared__ float sB[NE];
    const int tid = threadIdx.x;
    const int b0  = blockIdx.x * 64;
    for (int i = tid; i < 64*G2; i += 128)
        sG[(i >> 7)*129 + (i & 127)] = g_g2[(size_t)b0*G2 + i];
    for (int i = tid; i < G2*NE; i += 128) sW[i] = gw3[i];
    if (tid < NE) sB[tid] = gb3[tid];
    __syncthreads();
    if (tid < 64) {
        float lg[NE];
#pragma unroll
        for (int j = 0; j < NE; j++) lg[j] = sB[j];
        for (int k = 0; k < G2; k++) {
            float gv = sG[tid*129 + k];
#pragma unroll
            for (int j = 0; j < NE; j++) lg[j] += gv * sW[k*NE + j];
        }
        int i0 = 0; float m0 = lg[0];
#pragma unroll
        for (int j = 1; j < NE; j++) if (lg[j] > m0) { m0 = lg[j]; i0 = j; }
        int i1 = -1; float m1 = -3.4e38f;
#pragma unroll
        for (int j = 0; j < NE; j++) if (j != i0 && lg[j] > m1) { m1 = lg[j]; i1 = j; }
        float e1  = expf(m1 - m0);
        float inv = 1.f / (1.f + e1);
        int b = b0 + tid;
        g_tidx[b*2+0] = i0; g_tidx[b*2+1] = i1;
        g_tw[b*2+0] = inv;  g_tw[b*2+1] = e1 * inv;
        atomicAdd(&g_counts[i0], 1);
        atomicAdd(&g_counts[i1], 1);
    }
}

// ---------------- prefix sums ----------------
__global__ void offsets_kernel()
{
    if (threadIdx.x == 0 && blockIdx.x == 0) {
        int o = 0, t128 = 0, t32 = 0;
        for (int e = 0; e < NE; e++) {
            g_off[e] = o; g_tile128[e] = t128; g_tile32[e] = t32;
            int c = g_counts[e];
            o += c; t128 += (c + 127) >> 7; t32 += (c + 31) >> 5;
        }
        g_off[NE] = o; g_tile128[NE] = t128; g_tile32[NE] = t32;
    }
}

// ---------------- scatter tokens into per-expert slot lists ----------------
__global__ __launch_bounds__(256)
void scatter_kernel()
{
    const int b    = blockIdx.x * 256 + threadIdx.x;
    const int lane = threadIdx.x & 31;
#pragma unroll
    for (int s = 0; s < 2; s++) {
        int   e = g_tidx[b*2 + s];
        float w = g_tw[b*2 + s];
#pragma unroll
        for (int ee = 0; ee < NE; ee++) {
            unsigned m = __ballot_sync(0xffffffffu, e == ee);
            if (e == ee) {
                int rank   = __popc(m & ((1u << lane) - 1u));
                int leader = __ffs(m) - 1;
                int base = 0;
                if (lane == leader) base = atomicAdd(&g_cursor[ee], __popc(m));
                base = __shfl_sync(m, base, leader);
                int p = g_off[ee] + base + rank;
                g_tok[p] = b; g_wt[p] = w;
            }
        }
    }
}

// ---------------- layer 4 (K=256, N=32) fused with weighted combine ----------------
__global__ __launch_bounds__(256)
void l4_combine_kernel(const float* __restrict__ W4, const float* __restrict__ B4,
                       float* __restrict__ out)
{
    const int bx = blockIdx.x;
    if (bx >= g_tile32[NE]) return;
    int e = 0;
    while (bx >= g_tile32[e+1]) e++;
    const int row0   = g_off[e] + (bx - g_tile32[e]) * 32;
    const int rowEnd = g_off[e+1];

    __shared__ float sW[E3*NA];   // 32 KB
    const float* We = W4 + (size_t)e * E3 * NA;
    for (int i = threadIdx.x; i < E3*NA/4; i += 256)
        *(float4*)&sW[i*4] = *(const float4*)&We[i*4];
    __syncthreads();

    const int r  = threadIdx.x >> 3;
    const int c4 = (threadIdx.x & 7) * 4;
    const int row = row0 + r;
    if (row >= rowEnd) return;

    const bf162* hh = (const bf162*)(g_h3h + (size_t)row * E3);
    const bf162* ll = (const bf162*)(g_h3l + (size_t)row * E3);
    float a0 = 0.f, a1 = 0.f, a2 = 0.f, a3 = 0.f;
#pragma unroll 4
    for (int k = 0; k < E3; k += 4) {
        float2 p0 = __bfloat1622float2(hh[k/2]);
        float2 p1 = __bfloat1622float2(hh[k/2+1]);
        float2 q0 = __bfloat1622float2(ll[k/2]);
        float2 q1 = __bfloat1622float2(ll[k/2+1]);
        float hv0 = p0.x + q0.x, hv1 = p0.y + q0.y;
        float hv2 = p1.x + q1.x, hv3 = p1.y + q1.y;
        float4 w0 = *(float4*)&sW[(k+0)*NA + c4];
        float4 w1 = *(float4*)&sW[(k+1)*NA + c4];
        float4 w2 = *(float4*)&sW[(k+2)*NA + c4];
        float4 w3 = *(float4*)&sW[(k+3)*NA + c4];
        a0 += hv0*w0.x + hv1*w1.x + hv2*w2.x + hv3*w3.x;
        a1 += hv0*w0.y + hv1*w1.y + hv2*w2.y + hv3*w3.y;
        a2 += hv0*w0.z + hv1*w1.z + hv2*w2.z + hv3*w3.z;
        a3 += hv0*w0.w + hv1*w1.w + hv2*w2.w + hv3*w3.w;
    }
    const int   tok = g_tok[row];
    const float w   = g_wt[row];
    float* o = out + (size_t)tok * NA + c4;
    atomicAdd(o+0, w*(a0 + B4[e*NA + c4 + 0]));
    atomicAdd(o+1, w*(a1 + B4[e*NA + c4 + 1]));
    atomicAdd(o+2, w*(a2 + B4[e*NA + c4 + 2]));
    atomicAdd(o+3, w*(a3 + B4[e*NA + c4 + 3]));
}

// ---------------- launch ----------------
static inline void split_launch(const float* x, bf16* hi, bf16* lo, size_t n) {
    int n4 = (int)(n / 4);
    split_kernel<<<(n4 + 255)/256, 256>>>((const float4*)x, (bf162*)hi, (bf162*)lo, n4);
}

extern "C" void kernel_launch(void* const* d_in, const int* in_sizes, int n_in,
                              void* d_out, int out_size)
{
    const float* obs = (const float*)d_in[0];
    const float* gw1 = (const float*)d_in[1];
    const float* gb1 = (const float*)d_in[2];
    const float* gw2 = (const float*)d_in[3];
    const float* gb2 = (const float*)d_in[4];
    const float* gw3 = (const float*)d_in[5];
    const float* gb3 = (const float*)d_in[6];
    const float* ew1 = (const float*)d_in[7];
    const float* eb1 = (const float*)d_in[8];
    const float* ew2 = (const float*)d_in[9];
    const float* eb2 = (const float*)d_in[10];
    const float* ew3 = (const float*)d_in[11];
    const float* eb3 = (const float*)d_in[12];
    const float* ew4 = (const float*)d_in[13];
    const float* eb4 = (const float*)d_in[14];
    float* out = (float*)d_out;

    // symbol addresses
    bf16 *obs_h, *obs_l, *gw1h, *gw1l, *gw2h, *gw2l;
    bf16 *ew1h, *ew1l, *ew2h, *ew2l, *ew3h, *ew3l;
    bf16 *g1h, *g1l, *h1h, *h1l, *h2h, *h2l, *h3h, *h3l;
    float *pg2;
    cudaGetSymbolAddress((void**)&obs_h, g_obs_h); cudaGetSymbolAddress((void**)&obs_l, g_obs_l);
    cudaGetSymbolAddress((void**)&gw1h, g_gw1h);   cudaGetSymbolAddress((void**)&gw1l, g_gw1l);
    cudaGetSymbolAddress((void**)&gw2h, g_gw2h);   cudaGetSymbolAddress((void**)&gw2l, g_gw2l);
    cudaGetSymbolAddress((void**)&ew1h, g_ew1h);   cudaGetSymbolAddress((void**)&ew1l, g_ew1l);
    cudaGetSymbolAddress((void**)&ew2h, g_ew2h);   cudaGetSymbolAddress((void**)&ew2l, g_ew2l);
    cudaGetSymbolAddress((void**)&ew3h, g_ew3h);   cudaGetSymbolAddress((void**)&ew3l, g_ew3l);
    cudaGetSymbolAddress((void**)&g1h, g_g1h);     cudaGetSymbolAddress((void**)&g1l, g_g1l);
    cudaGetSymbolAddress((void**)&h1h, g_h1h);     cudaGetSymbolAddress((void**)&h1l, g_h1l);
    cudaGetSymbolAddress((void**)&h2h, g_h2h);     cudaGetSymbolAddress((void**)&h2l, g_h2l);
    cudaGetSymbolAddress((void**)&h3h, g_h3h);     cudaGetSymbolAddress((void**)&h3l, g_h3l);
    cudaGetSymbolAddress((void**)&pg2, g_g2);

    init_kernel<<<1, 32>>>();
    cudaMemsetAsync(out, 0, (size_t)out_size * sizeof(float));

    // splits
    split_launch(obs, obs_h, obs_l, (size_t)BB*DOBS);
    split_launch(gw1, gw1h, gw1l, (size_t)DOBS*G1);
    split_launch(gw2, gw2h, gw2l, (size_t)G1*G2);
    split_launch(ew1, ew1h, ew1l, (size_t)NE*DOBS*E1);
    split_launch(ew2, ew2h, ew2l, (size_t)NE*E1*E2);
    split_launch(ew3, ew3h, ew3l, (size_t)NE*E2*E3);

    // gating MLP (tensor core)
    mma_gemm<false,false,true ><<<dim3(BB/128, G1/128), 256>>>(
        obs_h, obs_l, gw1h, gw1l, gb1, g1h, g1l, nullptr, BB, DOBS, G1);
    mma_gemm<false,false,false><<<dim3(BB/128, G2/128), 256>>>(
        g1h, g1l, gw2h, gw2l, gb2, nullptr, nullptr, pg2, BB, G1, G2);
    gate_topk_kernel<<<BB/64, 128>>>(gw3, gb3);
    offsets_kernel<<<1, 32>>>();
    scatter_kernel<<<BB/256, 256>>>();

    // grouped expert layers (upper-bound grids; extra blocks exit early)
    const int T128 = NP/128 + NE;   // 264
    const int T32  = NP/32  + NE;   // 1032
    mma_gemm<true,true ,true><<<dim3(T128, E1/128), 256>>>(
        obs_h, obs_l, ew1h, ew1l, eb1, h1h, h1l, nullptr, 0, DOBS, E1);
    mma_gemm<true,false,true><<<dim3(T128, E2/128), 256>>>(
        h1h, h1l, ew2h, ew2l, eb2, h2h, h2l, nullptr, 0, E1, E2);
    mma_gemm<true,false,true><<<dim3(T128, E3/128), 256>>>(
        h2h, h2l, ew3h, ew3l, eb3, h3h, h3l, nullptr, 0, E2, E3);

    // layer 4 + weighted combine
    l4_combine_kernel<<<T32, 256>>>(ew4, eb4, out);
}

// round 6
// speedup vs baseline: 2.5132x; 1.3779x over previous
#include <cuda_runtime.h>
#include <cuda_fp16.h>
#include <cstdint>

#define BB   16384
#define DOBS 512
#define NE   8
#define NA   32
#define G1   256
#define G2   128
#define E1   1024
#define E2   512
#define E3   256
#define NP   (2*BB)

typedef __half h16;

// ---------------- scratch ----------------
__device__ __align__(16) h16 g_obs_h[BB*DOBS], g_obs_l[BB*DOBS];
// weights: fp16 hi/lo, natural [K,N] layout (per expert)
__device__ __align__(16) h16 g_gw1h[DOBS*G1], g_gw1l[DOBS*G1];
__device__ __align__(16) h16 g_gw2h[G1*G2],   g_gw2l[G1*G2];
__device__ __align__(16) h16 g_ew1h[NE*DOBS*E1], g_ew1l[NE*DOBS*E1];
__device__ __align__(16) h16 g_ew2h[NE*E1*E2],   g_ew2l[NE*E1*E2];
__device__ __align__(16) h16 g_ew3h[NE*E2*E3],   g_ew3l[NE*E2*E3];

__device__ __align__(16) h16 g_g1h[BB*G1], g_g1l[BB*G1];
__device__ __align__(16) float g_g2[BB*G2];
__device__ __align__(16) h16 g_h1h[(size_t)NP*E1], g_h1l[(size_t)NP*E1];
__device__ __align__(16) h16 g_h2h[(size_t)NP*E2], g_h2l[(size_t)NP*E2];
__device__ __align__(16) h16 g_h3h[(size_t)NP*E3], g_h3l[(size_t)NP*E3];

__device__ int   g_tidx[BB*2];
__device__ float g_tw[BB*2];
__device__ int   g_counts[NE];
__device__ int   g_off[NE+1];
__device__ int   g_tile128[NE+1];
__device__ int   g_tile32[NE+1];
__device__ int   g_cursor[NE];
__device__ int   g_tok[NP];
__device__ float g_wt[NP];

__device__ __forceinline__ float eluf(float x) { return x > 0.f ? x : expm1f(x); }

// ---------------- PTX helpers ----------------
__device__ __forceinline__ void mma_f16(float* c, const unsigned* a, const unsigned* b) {
    asm volatile(
        "mma.sync.aligned.m16n8k16.row.col.f32.f16.f16.f32 "
        "{%0,%1,%2,%3}, {%4,%5,%6,%7}, {%8,%9}, {%0,%1,%2,%3};"
        : "+f"(c[0]), "+f"(c[1]), "+f"(c[2]), "+f"(c[3])
        : "r"(a[0]), "r"(a[1]), "r"(a[2]), "r"(a[3]), "r"(b[0]), "r"(b[1]));
}
__device__ __forceinline__ void ldsm_x4(unsigned* r, unsigned addr) {
    asm volatile("ldmatrix.sync.aligned.m8n8.x4.shared.b16 {%0,%1,%2,%3}, [%4];"
                 : "=r"(r[0]), "=r"(r[1]), "=r"(r[2]), "=r"(r[3]) : "r"(addr));
}
__device__ __forceinline__ void ldsm_x4_t(unsigned* r, unsigned addr) {
    asm volatile("ldmatrix.sync.aligned.m8n8.x4.trans.shared.b16 {%0,%1,%2,%3}, [%4];"
                 : "=r"(r[0]), "=r"(r[1]), "=r"(r[2]), "=r"(r[3]) : "r"(addr));
}
__device__ __forceinline__ uint32_t s2u(const void* p) {
    uint32_t a;
    asm("{ .reg .u64 t; cvta.to.shared.u64 t, %1; cvt.u32.u64 %0, t; }" : "=r"(a) : "l"(p));
    return a;
}
__device__ __forceinline__ void cpa16(uint32_t dst, const void* src, uint32_t sz) {
    asm volatile("cp.async.cg.shared.global [%0], [%1], 16, %2;" :: "r"(dst), "l"(src), "r"(sz) : "memory");
}
__device__ __forceinline__ void cpcommit() { asm volatile("cp.async.commit_group;" ::: "memory"); }
template<int N> __device__ __forceinline__ void cpwait() { asm volatile("cp.async.wait_group %0;" :: "n"(N) : "memory"); }

// ---------------- split fp32 -> (hi, lo) fp16 ----------------
__global__ __launch_bounds__(256)
void split_kernel(const float4* __restrict__ x, __half2* __restrict__ hi,
                  __half2* __restrict__ lo, int n4)
{
    int i = blockIdx.x * 256 + threadIdx.x;
    if (i >= n4) return;
    float4 v = x[i];
    h16 h0 = __float2half_rn(v.x), h1 = __float2half_rn(v.y);
    h16 h2 = __float2half_rn(v.z), h3 = __float2half_rn(v.w);
    hi[2*i]   = __halves2half2(h0, h1);
    hi[2*i+1] = __halves2half2(h2, h3);
    lo[2*i]   = __halves2half2(__float2half_rn(v.x - __half2float(h0)),
                               __float2half_rn(v.y - __half2float(h1)));
    lo[2*i+1] = __halves2half2(__float2half_rn(v.z - __half2float(h2)),
                               __float2half_rn(v.w - __half2float(h3)));
}

// ---------------- init ----------------
__global__ void init_kernel() {
    int t = threadIdx.x;
    if (t < NE) { g_counts[t] = 0; g_cursor[t] = 0; }
}

// ---------------- pipelined fp16 tensor-core grouped GEMM (3-pass split) ----------------
// C = ELU(Ah@Wh + Ah@Wl + Al@Wh + bias). CTA tile 128x128, BK=32, 3-stage cp.async.
// 256 threads = 8 warps: warpM = wid&3 (32 rows), warpN = wid>>2 (64 cols).
// stage: Ah[128][40] 10240 | Al 10240 | Bh[32][136] 8704 | Bl 8704 = 37888 B
#define STG     37888
#define AL_OFF  10240
#define BH_OFF  20480
#define BL_OFF  29184
#define SMEM_DYN (3*STG)

template<bool GROUPED, bool GATHER, bool OUTSPLIT>
__global__ __launch_bounds__(256)
void mma_gemm(const h16* __restrict__ Ah, const h16* __restrict__ Al,
              const h16* __restrict__ Wh, const h16* __restrict__ Wl,
              const float* __restrict__ bias,
              h16* __restrict__ Ch, h16* __restrict__ Cl, float* __restrict__ Cf,
              int M, int K, int N)
{
    extern __shared__ __align__(128) char sm[];
    int row0, rowEnd;
    if (GROUPED) {
        int bx = blockIdx.x;
        if (bx >= g_tile128[NE]) return;
        int e = 0;
        while (bx >= g_tile128[e+1]) e++;
        row0   = g_off[e] + (bx - g_tile128[e]) * 128;
        rowEnd = g_off[e+1];
        if (row0 >= rowEnd) return;
        Wh   += (size_t)e * K * N;
        Wl   += (size_t)e * K * N;
        bias += e * N;
    } else {
        row0   = blockIdx.x * 128;
        rowEnd = M;
    }
    const int n0  = blockIdx.y * 128;
    const int tid = threadIdx.x, lane = tid & 31, wid = tid >> 5;
    const int warpM = wid & 3, warpN = wid >> 2;
    const uint32_t su = s2u(sm);

    // --- A load mapping: 2 rows/thread (r, r+64), chunk ch of 4x16B per 64B row
    const int ar  = tid >> 2;
    const int ach = tid & 3;
    const h16 *pAh[2], *pAl[2];
    uint32_t asz[2];
#pragma unroll
    for (int i = 0; i < 2; i++) {
        int gr = row0 + ar + 64*i;
        bool v = gr < rowEnd;
        asz[i] = v ? 16u : 0u;
        size_t rowIdx = 0;
        if (v) rowIdx = GATHER ? (size_t)g_tok[gr] : (size_t)gr;
        pAh[i] = Ah + rowIdx * K + ach*8;
        pAl[i] = Al + rowIdx * K + ach*8;
    }
    // --- B load mapping: 2 k-rows/thread (k, k+16), chunk of 16x16B per 256B row
    const int br  = tid >> 4;
    const int bch = tid & 15;
    const h16* pBh = Wh + (size_t)br * N + n0 + bch*8;
    const h16* pBl = Wl + (size_t)br * N + n0 + bch*8;

    float acc[2][8][4];
#pragma unroll
    for (int mt = 0; mt < 2; mt++)
#pragma unroll
        for (int nt = 0; nt < 8; nt++)
#pragma unroll
            for (int q = 0; q < 4; q++) acc[mt][nt][q] = 0.f;

    const int S = K >> 5;

    auto LOAD = [&](int t) {
        uint32_t base = su + (uint32_t)(t % 3) * STG;
        int kf = t * 32;
#pragma unroll
        for (int i = 0; i < 2; i++) {
            uint32_t d = base + (uint32_t)((ar + 64*i)*80 + ach*16);
            cpa16(d,          pAh[i] + kf, asz[i]);
            cpa16(d + AL_OFF, pAl[i] + kf, asz[i]);
        }
#pragma unroll
        for (int i = 0; i < 2; i++) {
            uint32_t d = base + (uint32_t)((br + 16*i)*272 + bch*16);
            cpa16(d + BH_OFF, pBh + (size_t)(kf + 16*i) * N, 16u);
            cpa16(d + BL_OFF, pBl + (size_t)(kf + 16*i) * N, 16u);
        }
        cpcommit();
    };

    LOAD(0);
    LOAD(1);

    for (int s = 0; s < S; s++) {
        __syncthreads();               // all warps done with buffer (s+2)%3
        int rem = S - 1 - s;
        if (rem >= 2) { LOAD(s+2); cpwait<2>(); }
        else if (rem == 1) cpwait<1>();
        else cpwait<0>();
        __syncthreads();               // stage s visible

        const uint32_t aBase = su + (uint32_t)(s % 3) * STG;
#pragma unroll
        for (int kk = 0; kk < 32; kk += 16) {
            unsigned ah[2][4], al[2][4];
#pragma unroll
            for (int mt = 0; mt < 2; mt++) {
                uint32_t off = (uint32_t)(((warpM*32 + mt*16 + (lane & 15))*40 + kk + 8*(lane >> 4)) * 2);
                ldsm_x4(ah[mt], aBase + off);
                ldsm_x4(al[mt], aBase + AL_OFF + off);
            }
            const int brow = kk + (lane & 15);
#pragma unroll
            for (int np = 0; np < 4; np++) {
                const int bcol = warpN*64 + np*16 + 8*(lane >> 4);
                uint32_t boff = (uint32_t)((brow*136 + bcol) * 2);
                unsigned bh[4], bl[4];
                ldsm_x4_t(bh, aBase + BH_OFF + boff);
                ldsm_x4_t(bl, aBase + BL_OFF + boff);
#pragma unroll
                for (int mt = 0; mt < 2; mt++) {
                    mma_f16(acc[mt][2*np],   ah[mt], bh);
                    mma_f16(acc[mt][2*np+1], ah[mt], bh+2);
                    mma_f16(acc[mt][2*np],   ah[mt], bl);
                    mma_f16(acc[mt][2*np+1], ah[mt], bl+2);
                    mma_f16(acc[mt][2*np],   al[mt], bh);
                    mma_f16(acc[mt][2*np+1], al[mt], bh+2);
                }
            }
        }
    }

    // ---------------- epilogue: bias + ELU + (hi,lo) split stores ----------------
#pragma unroll
    for (int mt = 0; mt < 2; mt++) {
        int r0 = row0 + warpM*32 + mt*16 + (lane >> 2);
#pragma unroll
        for (int nt = 0; nt < 8; nt++) {
            int c = n0 + warpN*64 + nt*8 + 2*(lane & 3);
            float b0 = __ldg(bias + c), b1 = __ldg(bias + c + 1);
            float v00 = eluf(acc[mt][nt][0] + b0);
            float v01 = eluf(acc[mt][nt][1] + b1);
            float v10 = eluf(acc[mt][nt][2] + b0);
            float v11 = eluf(acc[mt][nt][3] + b1);
            if (r0 < rowEnd) {
                if (OUTSPLIT) {
                    h16 h0 = __float2half_rn(v00), h1 = __float2half_rn(v01);
                    *(__half2*)(Ch + (size_t)r0*N + c) = __halves2half2(h0, h1);
                    *(__half2*)(Cl + (size_t)r0*N + c) =
                        __halves2half2(__float2half_rn(v00 - __half2float(h0)),
                                       __float2half_rn(v01 - __half2float(h1)));
                } else {
                    *(float2*)(Cf + (size_t)r0*N + c) = make_float2(v00, v01);
                }
            }
            if (r0 + 8 < rowEnd) {
                if (OUTSPLIT) {
                    h16 h0 = __float2half_rn(v10), h1 = __float2half_rn(v11);
                    *(__half2*)(Ch + (size_t)(r0+8)*N + c) = __halves2half2(h0, h1);
                    *(__half2*)(Cl + (size_t)(r0+8)*N + c) =
                        __halves2half2(__float2half_rn(v10 - __half2float(h0)),
                                       __float2half_rn(v11 - __half2float(h1)));
                } else {
                    *(float2*)(Cf + (size_t)(r0+8)*N + c) = make_float2(v10, v11);
                }
            }
        }
    }
}

// ---------------- gating head: logits + top-2 + renorm + counts ----------------
__global__ __launch_bounds__(128)
void gate_topk_kernel(const float* __restrict__ gw3, const float* __restrict__ gb3)
{
    __shared__ float sG[64*129];
    __shared__ float sW[G2*NE];
    __shared__ float sB[NE];
    const int tid = threadIdx.x;
    const int b0  = blockIdx.x * 64;
    for (int i = tid; i < 64*G2; i += 128)
        sG[(i >> 7)*129 + (i & 127)] = g_g2[(size_t)b0*G2 + i];
    for (int i = tid; i < G2*NE; i += 128) sW[i] = gw3[i];
    if (tid < NE) sB[tid] = gb3[tid];
    __syncthreads();
    if (tid < 64) {
        float lg[NE];
#pragma unroll
        for (int j = 0; j < NE; j++) lg[j] = sB[j];
        for (int k = 0; k < G2; k++) {
            float gv = sG[tid*129 + k];
#pragma unroll
            for (int j = 0; j < NE; j++) lg[j] += gv * sW[k*NE + j];
        }
        int i0 = 0; float m0 = lg[0];
#pragma unroll
        for (int j = 1; j < NE; j++) if (lg[j] > m0) { m0 = lg[j]; i0 = j; }
        int i1 = -1; float m1 = -3.4e38f;
#pragma unroll
        for (int j = 0; j < NE; j++) if (j != i0 && lg[j] > m1) { m1 = lg[j]; i1 = j; }
        float e1  = expf(m1 - m0);
        float inv = 1.f / (1.f + e1);
        int b = b0 + tid;
        g_tidx[b*2+0] = i0; g_tidx[b*2+1] = i1;
        g_tw[b*2+0] = inv;  g_tw[b*2+1] = e1 * inv;
        atomicAdd(&g_counts[i0], 1);
        atomicAdd(&g_counts[i1], 1);
    }
}

// ---------------- prefix sums ----------------
__global__ void offsets_kernel()
{
    if (threadIdx.x == 0 && blockIdx.x == 0) {
        int o = 0, t128 = 0, t32 = 0;
        for (int e = 0; e < NE; e++) {
            g_off[e] = o; g_tile128[e] = t128; g_tile32[e] = t32;
            int c = g_counts[e];
            o += c; t128 += (c + 127) >> 7; t32 += (c + 31) >> 5;
        }
        g_off[NE] = o; g_tile128[NE] = t128; g_tile32[NE] = t32;
    }
}

// ---------------- scatter ----------------
__global__ __launch_bounds__(256)
void scatter_kernel()
{
    const int b    = blockIdx.x * 256 + threadIdx.x;
    const int lane = threadIdx.x & 31;
#pragma unroll
    for (int s = 0; s < 2; s++) {
        int   e = g_tidx[b*2 + s];
        float w = g_tw[b*2 + s];
#pragma unroll
        for (int ee = 0; ee < NE; ee++) {
            unsigned m = __ballot_sync(0xffffffffu, e == ee);
            if (e == ee) {
                int rank   = __popc(m & ((1u << lane) - 1u));
                int leader = __ffs(m) - 1;
                int base = 0;
                if (lane == leader) base = atomicAdd(&g_cursor[ee], __popc(m));
                base = __shfl_sync(m, base, leader);
                int p = g_off[ee] + base + rank;
                g_tok[p] = b; g_wt[p] = w;
            }
        }
    }
}

// ---------------- layer 4 (K=256, N=32) + weighted combine ----------------
__global__ __launch_bounds__(256)
void l4_combine_kernel(const float* __restrict__ W4, const float* __restrict__ B4,
                       float* __restrict__ out)
{
    const int bx = blockIdx.x;
    if (bx >= g_tile32[NE]) return;
    int e = 0;
    while (bx >= g_tile32[e+1]) e++;
    const int row0   = g_off[e] + (bx - g_tile32[e]) * 32;
    const int rowEnd = g_off[e+1];

    __shared__ float sW[E3*NA];
    const float* We = W4 + (size_t)e * E3 * NA;
    for (int i = threadIdx.x; i < E3*NA/4; i += 256)
        *(float4*)&sW[i*4] = *(const float4*)&We[i*4];
    __syncthreads();

    const int r  = threadIdx.x >> 3;
    const int c4 = (threadIdx.x & 7) * 4;
    const int row = row0 + r;
    if (row >= rowEnd) return;

    const __half2* hh = (const __half2*)(g_h3h + (size_t)row * E3);
    const __half2* ll = (const __half2*)(g_h3l + (size_t)row * E3);
    float a0 = 0.f, a1 = 0.f, a2 = 0.f, a3 = 0.f;
#pragma unroll 4
    for (int k = 0; k < E3; k += 4) {
        float2 p0 = __half22float2(hh[k/2]);
        float2 p1 = __half22float2(hh[k/2+1]);
        float2 q0 = __half22float2(ll[k/2]);
        float2 q1 = __half22float2(ll[k/2+1]);
        float hv0 = p0.x + q0.x, hv1 = p0.y + q0.y;
        float hv2 = p1.x + q1.x, hv3 = p1.y + q1.y;
        float4 w0 = *(float4*)&sW[(k+0)*NA + c4];
        float4 w1 = *(float4*)&sW[(k+1)*NA + c4];
        float4 w2 = *(float4*)&sW[(k+2)*NA + c4];
        float4 w3 = *(float4*)&sW[(k+3)*NA + c4];
        a0 += hv0*w0.x + hv1*w1.x + hv2*w2.x + hv3*w3.x;
        a1 += hv0*w0.y + hv1*w1.y + hv2*w2.y + hv3*w3.y;
        a2 += hv0*w0.z + hv1*w1.z + hv2*w2.z + hv3*w3.z;
        a3 += hv0*w0.w + hv1*w1.w + hv2*w2.w + hv3*w3.w;
    }
    const int   tok = g_tok[row];
    const float w   = g_wt[row];
    float* o = out + (size_t)tok * NA + c4;
    atomicAdd(o+0, w*(a0 + B4[e*NA + c4 + 0]));
    atomicAdd(o+1, w*(a1 + B4[e*NA + c4 + 1]));
    atomicAdd(o+2, w*(a2 + B4[e*NA + c4 + 2]));
    atomicAdd(o+3, w*(a3 + B4[e*NA + c4 + 3]));
}

// ---------------- launch ----------------
static inline void split_launch(const float* x, h16* hi, h16* lo, size_t n) {
    int n4 = (int)(n / 4);
    split_kernel<<<(n4 + 255)/256, 256>>>((const float4*)x, (__half2*)hi, (__half2*)lo, n4);
}

extern "C" void kernel_launch(void* const* d_in, const int* in_sizes, int n_in,
                              void* d_out, int out_size)
{
    const float* obs = (const float*)d_in[0];
    const float* gw1 = (const float*)d_in[1];
    const float* gb1 = (const float*)d_in[2];
    const float* gw2 = (const float*)d_in[3];
    const float* gb2 = (const float*)d_in[4];
    const float* gw3 = (const float*)d_in[5];
    const float* gb3 = (const float*)d_in[6];
    const float* ew1 = (const float*)d_in[7];
    const float* eb1 = (const float*)d_in[8];
    const float* ew2 = (const float*)d_in[9];
    const float* eb2 = (const float*)d_in[10];
    const float* ew3 = (const float*)d_in[11];
    const float* eb3 = (const float*)d_in[12];
    const float* ew4 = (const float*)d_in[13];
    const float* eb4 = (const float*)d_in[14];
    float* out = (float*)d_out;

    h16 *obs_h, *obs_l, *gw1h, *gw1l, *gw2h, *gw2l;
    h16 *ew1h, *ew1l, *ew2h, *ew2l, *ew3h, *ew3l;
    h16 *g1h, *g1l, *h1h, *h1l, *h2h, *h2l, *h3h, *h3l;
    float *pg2;
    cudaGetSymbolAddress((void**)&obs_h, g_obs_h); cudaGetSymbolAddress((void**)&obs_l, g_obs_l);
    cudaGetSymbolAddress((void**)&gw1h, g_gw1h);   cudaGetSymbolAddress((void**)&gw1l, g_gw1l);
    cudaGetSymbolAddress((void**)&gw2h, g_gw2h);   cudaGetSymbolAddress((void**)&gw2l, g_gw2l);
    cudaGetSymbolAddress((void**)&ew1h, g_ew1h);   cudaGetSymbolAddress((void**)&ew1l, g_ew1l);
    cudaGetSymbolAddress((void**)&ew2h, g_ew2h);   cudaGetSymbolAddress((void**)&ew2l, g_ew2l);
    cudaGetSymbolAddress((void**)&ew3h, g_ew3h);   cudaGetSymbolAddress((void**)&ew3l, g_ew3l);
    cudaGetSymbolAddress((void**)&g1h, g_g1h);     cudaGetSymbolAddress((void**)&g1l, g_g1l);
    cudaGetSymbolAddress((void**)&h1h, g_h1h);     cudaGetSymbolAddress((void**)&h1l, g_h1l);
    cudaGetSymbolAddress((void**)&h2h, g_h2h);     cudaGetSymbolAddress((void**)&h2l, g_h2l);
    cudaGetSymbolAddress((void**)&h3h, g_h3h);     cudaGetSymbolAddress((void**)&h3l, g_h3l);
    cudaGetSymbolAddress((void**)&pg2, g_g2);

    cudaFuncSetAttribute(mma_gemm<false,false,true >, cudaFuncAttributeMaxDynamicSharedMemorySize, SMEM_DYN);
    cudaFuncSetAttribute(mma_gemm<false,false,false>, cudaFuncAttributeMaxDynamicSharedMemorySize, SMEM_DYN);
    cudaFuncSetAttribute(mma_gemm<true ,true ,true >, cudaFuncAttributeMaxDynamicSharedMemorySize, SMEM_DYN);
    cudaFuncSetAttribute(mma_gemm<true ,false,true >, cudaFuncAttributeMaxDynamicSharedMemorySize, SMEM_DYN);

    init_kernel<<<1, 32>>>();
    cudaMemsetAsync(out, 0, (size_t)out_size * sizeof(float));

    // operand prep (hi/lo splits)
    split_launch(obs, obs_h, obs_l, (size_t)BB*DOBS);
    split_launch(gw1, gw1h, gw1l, (size_t)DOBS*G1);
    split_launch(gw2, gw2h, gw2l, (size_t)G1*G2);
    split_launch(ew1, ew1h, ew1l, (size_t)NE*DOBS*E1);
    split_launch(ew2, ew2h, ew2l, (size_t)NE*E1*E2);
    split_launch(ew3, ew3h, ew3l, (size_t)NE*E2*E3);

    // gating MLP
    mma_gemm<false,false,true ><<<dim3(BB/128, G1/128), 256, SMEM_DYN>>>(
        obs_h, obs_l, gw1h, gw1l, gb1, g1h, g1l, nullptr, BB, DOBS, G1);
    mma_gemm<false,false,false><<<dim3(BB/128, G2/128), 256, SMEM_DYN>>>(
        g1h, g1l, gw2h, gw2l, gb2, nullptr, nullptr, pg2, BB, G1, G2);
    gate_topk_kernel<<<BB/64, 128>>>(gw3, gb3);
    offsets_kernel<<<1, 32>>>();
    scatter_kernel<<<BB/256, 256>>>();

    // grouped expert layers
    const int T128 = NP/128 + NE;   // 264
    const int T32  = NP/32  + NE;   // 1032
    mma_gemm<true,true ,true><<<dim3(T128, E1/128), 256, SMEM_DYN>>>(
        obs_h, obs_l, ew1h, ew1l, eb1, h1h, h1l, nullptr, 0, DOBS, E1);
    mma_gemm<true,false,true><<<dim3(T128, E2/128), 256, SMEM_DYN>>>(
        h1h, h1l, ew2h, ew2l, eb2, h2h, h2l, nullptr, 0, E1, E2);
    mma_gemm<true,false,true><<<dim3(T128, E3/128), 256, SMEM_DYN>>>(
        h2h, h2l, ew3h, ew3l, eb3, h3h, h3l, nullptr, 0, E2, E3);

    // layer 4 + weighted combine
    l4_combine_kernel<<<T32, 256>>>(ew4, eb4, out);
}

// round 7
// speedup vs baseline: 3.5829x; 1.4256x over previous
#include <cuda_runtime.h>
#include <cuda_fp16.h>
#include <cstdint>

#define BB   16384
#define DOBS 512
#define NE   8
#define NA   32
#define G1   256
#define G2   128
#define E1   1024
#define E2   512
#define E3   256
#define NP   (2*BB)

typedef __half h16;

// ---------------- scratch ----------------
__device__ __align__(16) h16 g_obs_h[BB*DOBS], g_obs_l[BB*DOBS];
// weights: fp16 hi/lo, natural [K,N] layout (per expert)
__device__ __align__(16) h16 g_gw1h[DOBS*G1], g_gw1l[DOBS*G1];
__device__ __align__(16) h16 g_gw2h[G1*G2],   g_gw2l[G1*G2];
__device__ __align__(16) h16 g_ew1h[NE*DOBS*E1], g_ew1l[NE*DOBS*E1];
__device__ __align__(16) h16 g_ew2h[NE*E1*E2],   g_ew2l[NE*E1*E2];
__device__ __align__(16) h16 g_ew3h[NE*E2*E3],   g_ew3l[NE*E2*E3];

__device__ __align__(16) h16 g_g1h[BB*G1], g_g1l[BB*G1];
__device__ __align__(16) float g_g2[BB*G2];
// expert activations: SINGLE fp16
__device__ __align__(16) h16 g_h1[(size_t)NP*E1];
__device__ __align__(16) h16 g_h2[(size_t)NP*E2];
__device__ __align__(16) h16 g_h3[(size_t)NP*E3];

__device__ int   g_tidx[BB*2];
__device__ float g_tw[BB*2];
__device__ int   g_counts[NE];
__device__ int   g_off[NE+1];
__device__ int   g_tile128[NE+1];
__device__ int   g_tile32[NE+1];
__device__ int   g_cursor[NE];
__device__ int   g_tok[NP];
__device__ float g_wt[NP];

__device__ __forceinline__ float eluf(float x) { return x > 0.f ? x : expm1f(x); }

// ---------------- PTX helpers ----------------
__device__ __forceinline__ void mma_f16(float* c, const unsigned* a, const unsigned* b) {
    asm volatile(
        "mma.sync.aligned.m16n8k16.row.col.f32.f16.f16.f32 "
        "{%0,%1,%2,%3}, {%4,%5,%6,%7}, {%8,%9}, {%0,%1,%2,%3};"
        : "+f"(c[0]), "+f"(c[1]), "+f"(c[2]), "+f"(c[3])
        : "r"(a[0]), "r"(a[1]), "r"(a[2]), "r"(a[3]), "r"(b[0]), "r"(b[1]));
}
__device__ __forceinline__ void ldsm_x4(unsigned* r, unsigned addr) {
    asm volatile("ldmatrix.sync.aligned.m8n8.x4.shared.b16 {%0,%1,%2,%3}, [%4];"
                 : "=r"(r[0]), "=r"(r[1]), "=r"(r[2]), "=r"(r[3]) : "r"(addr));
}
__device__ __forceinline__ void ldsm_x4_t(unsigned* r, unsigned addr) {
    asm volatile("ldmatrix.sync.aligned.m8n8.x4.trans.shared.b16 {%0,%1,%2,%3}, [%4];"
                 : "=r"(r[0]), "=r"(r[1]), "=r"(r[2]), "=r"(r[3]) : "r"(addr));
}
__device__ __forceinline__ uint32_t s2u(const void* p) {
    uint32_t a;
    asm("{ .reg .u64 t; cvta.to.shared.u64 t, %1; cvt.u32.u64 %0, t; }" : "=r"(a) : "l"(p));
    return a;
}
__device__ __forceinline__ void cpa16(uint32_t dst, const void* src, uint32_t sz) {
    asm volatile("cp.async.cg.shared.global [%0], [%1], 16, %2;" :: "r"(dst), "l"(src), "r"(sz) : "memory");
}
__device__ __forceinline__ void cpcommit() { asm volatile("cp.async.commit_group;" ::: "memory"); }
template<int N> __device__ __forceinline__ void cpwait() { asm volatile("cp.async.wait_group %0;" :: "n"(N) : "memory"); }

// ---------------- split fp32 -> (hi, lo) fp16 ----------------
__global__ __launch_bounds__(256)
void split_kernel(const float4* __restrict__ x, __half2* __restrict__ hi,
                  __half2* __restrict__ lo, int n4)
{
    int i = blockIdx.x * 256 + threadIdx.x;
    if (i >= n4) return;
    float4 v = x[i];
    h16 h0 = __float2half_rn(v.x), h1 = __float2half_rn(v.y);
    h16 h2 = __float2half_rn(v.z), h3 = __float2half_rn(v.w);
    hi[2*i]   = __halves2half2(h0, h1);
    hi[2*i+1] = __halves2half2(h2, h3);
    lo[2*i]   = __halves2half2(__float2half_rn(v.x - __half2float(h0)),
                               __float2half_rn(v.y - __half2float(h1)));
    lo[2*i+1] = __halves2half2(__float2half_rn(v.z - __half2float(h2)),
                               __float2half_rn(v.w - __half2float(h3)));
}

// ---------------- init ----------------
__global__ void init_kernel() {
    int t = threadIdx.x;
    if (t < NE) { g_counts[t] = 0; g_cursor[t] = 0; }
}

// ---------------- pipelined fp16 TC grouped GEMM ----------------
// ASPLIT=1 (gating, 3-pass): C = Ah@Wh + Ah@Wl + Al@Wh
// ASPLIT=0 (experts, 2-pass): C = A@Wh + A@Wl  (W split => W exact to ~2^-22)
// CTA tile 128x128, BK=32, 3-stage cp.async. 256 thr, warpM=wid&3, warpN=wid>>2.
// OUTM: 0 = fp16 single, 1 = fp16 hi/lo, 2 = fp32
#define A_BYTES 10240   // 128 x 40 halves
#define B_BYTES 8704    // 32 x 136 halves

template<bool GROUPED, bool GATHER, bool ASPLIT, int OUTM>
__global__ __launch_bounds__(256)
void mma_gemm(const h16* __restrict__ Ah, const h16* __restrict__ Al,
              const h16* __restrict__ Wh, const h16* __restrict__ Wl,
              const float* __restrict__ bias,
              h16* __restrict__ Ch, h16* __restrict__ Cl, float* __restrict__ Cf,
              int M, int K, int N)
{
    constexpr uint32_t AL_OFF = A_BYTES;
    constexpr uint32_t BH_OFF = ASPLIT ? 2*A_BYTES : A_BYTES;
    constexpr uint32_t BL_OFF = BH_OFF + B_BYTES;
    constexpr uint32_t STG    = BL_OFF + B_BYTES;

    extern __shared__ __align__(128) char sm[];
    int row0, rowEnd;
    if (GROUPED) {
        int bx = blockIdx.x;
        if (bx >= g_tile128[NE]) return;
        int e = 0;
        while (bx >= g_tile128[e+1]) e++;
        row0   = g_off[e] + (bx - g_tile128[e]) * 128;
        rowEnd = g_off[e+1];
        if (row0 >= rowEnd) return;
        Wh   += (size_t)e * K * N;
        Wl   += (size_t)e * K * N;
        bias += e * N;
    } else {
        row0   = blockIdx.x * 128;
        rowEnd = M;
    }
    const int n0  = blockIdx.y * 128;
    const int tid = threadIdx.x, lane = tid & 31, wid = tid >> 5;
    const int warpM = wid & 3, warpN = wid >> 2;
    const uint32_t su = s2u(sm);

    // A load mapping: 2 rows/thread (r, r+64), chunk ach of 4x16B per 64B row
    const int ar  = tid >> 2;
    const int ach = tid & 3;
    const h16 *pAh[2], *pAl[2];
    uint32_t asz[2];
#pragma unroll
    for (int i = 0; i < 2; i++) {
        int gr = row0 + ar + 64*i;
        bool v = gr < rowEnd;
        asz[i] = v ? 16u : 0u;
        size_t rowIdx = 0;
        if (v) rowIdx = GATHER ? (size_t)g_tok[gr] : (size_t)gr;
        pAh[i] = Ah + rowIdx * K + ach*8;
        if (ASPLIT) pAl[i] = Al + rowIdx * K + ach*8;
    }
    // B load mapping: 2 k-rows/thread (k, k+16), chunk of 16x16B per 256B row
    const int br  = tid >> 4;
    const int bch = tid & 15;
    const h16* pBh = Wh + (size_t)br * N + n0 + bch*8;
    const h16* pBl = Wl + (size_t)br * N + n0 + bch*8;

    float acc[2][8][4];
#pragma unroll
    for (int mt = 0; mt < 2; mt++)
#pragma unroll
        for (int nt = 0; nt < 8; nt++)
#pragma unroll
            for (int q = 0; q < 4; q++) acc[mt][nt][q] = 0.f;

    const int S = K >> 5;

    auto LOAD = [&](int t) {
        uint32_t base = su + (uint32_t)(t % 3) * STG;
        int kf = t * 32;
#pragma unroll
        for (int i = 0; i < 2; i++) {
            uint32_t d = base + (uint32_t)((ar + 64*i)*80 + ach*16);
            cpa16(d, pAh[i] + kf, asz[i]);
            if (ASPLIT) cpa16(d + AL_OFF, pAl[i] + kf, asz[i]);
        }
#pragma unroll
        for (int i = 0; i < 2; i++) {
            uint32_t d = base + (uint32_t)((br + 16*i)*272 + bch*16);
            cpa16(d + BH_OFF, pBh + (size_t)(kf + 16*i) * N, 16u);
            cpa16(d + BL_OFF, pBl + (size_t)(kf + 16*i) * N, 16u);
        }
        cpcommit();
    };

    LOAD(0);
    LOAD(1);

    for (int s = 0; s < S; s++) {
        __syncthreads();               // all warps done with buffer (s+2)%3
        int rem = S - 1 - s;
        if (rem >= 2) { LOAD(s+2); cpwait<2>(); }
        else if (rem == 1) cpwait<1>();
        else cpwait<0>();
        __syncthreads();               // stage s visible

        const uint32_t aBase = su + (uint32_t)(s % 3) * STG;
#pragma unroll
        for (int kk = 0; kk < 32; kk += 16) {
            unsigned ah[2][4], al[2][4];
#pragma unroll
            for (int mt = 0; mt < 2; mt++) {
                uint32_t off = (uint32_t)(((warpM*32 + mt*16 + (lane & 15))*40 + kk + 8*(lane >> 4)) * 2);
                ldsm_x4(ah[mt], aBase + off);
                if (ASPLIT) ldsm_x4(al[mt], aBase + AL_OFF + off);
            }
            const int brow = kk + (lane & 15);
#pragma unroll
            for (int np = 0; np < 4; np++) {
                const int bcol = warpN*64 + np*16 + 8*(lane >> 4);
                uint32_t boff = (uint32_t)((brow*136 + bcol) * 2);
                unsigned bh[4], bl[4];
                ldsm_x4_t(bh, aBase + BH_OFF + boff);
                ldsm_x4_t(bl, aBase + BL_OFF + boff);
#pragma unroll
                for (int mt = 0; mt < 2; mt++) {
                    mma_f16(acc[mt][2*np],   ah[mt], bh);
                    mma_f16(acc[mt][2*np+1], ah[mt], bh+2);
                    mma_f16(acc[mt][2*np],   ah[mt], bl);
                    mma_f16(acc[mt][2*np+1], ah[mt], bl+2);
                    if (ASPLIT) {
                        mma_f16(acc[mt][2*np],   al[mt], bh);
                        mma_f16(acc[mt][2*np+1], al[mt], bh+2);
                    }
                }
            }
        }
    }

    // ---------------- epilogue ----------------
#pragma unroll
    for (int mt = 0; mt < 2; mt++) {
        int r0 = row0 + warpM*32 + mt*16 + (lane >> 2);
#pragma unroll
        for (int nt = 0; nt < 8; nt++) {
            int c = n0 + warpN*64 + nt*8 + 2*(lane & 3);
            float b0 = __ldg(bias + c), b1 = __ldg(bias + c + 1);
            float v00 = eluf(acc[mt][nt][0] + b0);
            float v01 = eluf(acc[mt][nt][1] + b1);
            float v10 = eluf(acc[mt][nt][2] + b0);
            float v11 = eluf(acc[mt][nt][3] + b1);
#pragma unroll
            for (int rr = 0; rr < 2; rr++) {
                int r = r0 + rr*8;
                float va = rr ? v10 : v00, vb = rr ? v11 : v01;
                if (r < rowEnd) {
                    if (OUTM == 0) {
                        *(__half2*)(Ch + (size_t)r*N + c) =
                            __halves2half2(__float2half_rn(va), __float2half_rn(vb));
                    } else if (OUTM == 1) {
                        h16 h0 = __float2half_rn(va), h1 = __float2half_rn(vb);
                        *(__half2*)(Ch + (size_t)r*N + c) = __halves2half2(h0, h1);
                        *(__half2*)(Cl + (size_t)r*N + c) =
                            __halves2half2(__float2half_rn(va - __half2float(h0)),
                                           __float2half_rn(vb - __half2float(h1)));
                    } else {
                        *(float2*)(Cf + (size_t)r*N + c) = make_float2(va, vb);
                    }
                }
            }
        }
    }
}

// ---------------- gating head: logits + top-2 + renorm + counts ----------------
__global__ __launch_bounds__(128)
void gate_topk_kernel(const float* __restrict__ gw3, const float* __restrict__ gb3)
{
    __shared__ float sG[64*129];
    __shared__ float sW[G2*NE];
    __shared__ float sB[NE];
    const int tid = threadIdx.x;
    const int b0  = blockIdx.x * 64;
    for (int i = tid; i < 64*G2; i += 128)
        sG[(i >> 7)*129 + (i & 127)] = g_g2[(size_t)b0*G2 + i];
    for (int i = tid; i < G2*NE; i += 128) sW[i] = gw3[i];
    if (tid < NE) sB[tid] = gb3[tid];
    __syncthreads();
    if (tid < 64) {
        float lg[NE];
#pragma unroll
        for (int j = 0; j < NE; j++) lg[j] = sB[j];
        for (int k = 0; k < G2; k++) {
            float gv = sG[tid*129 + k];
#pragma unroll
            for (int j = 0; j < NE; j++) lg[j] += gv * sW[k*NE + j];
        }
        int i0 = 0; float m0 = lg[0];
#pragma unroll
        for (int j = 1; j < NE; j++) if (lg[j] > m0) { m0 = lg[j]; i0 = j; }
        int i1 = -1; float m1 = -3.4e38f;
#pragma unroll
        for (int j = 0; j < NE; j++) if (j != i0 && lg[j] > m1) { m1 = lg[j]; i1 = j; }
        float e1  = expf(m1 - m0);
        float inv = 1.f / (1.f + e1);
        int b = b0 + tid;
        g_tidx[b*2+0] = i0; g_tidx[b*2+1] = i1;
        g_tw[b*2+0] = inv;  g_tw[b*2+1] = e1 * inv;
        atomicAdd(&g_counts[i0], 1);
        atomicAdd(&g_counts[i1], 1);
    }
}

// ---------------- prefix sums ----------------
__global__ void offsets_kernel()
{
    if (threadIdx.x == 0 && blockIdx.x == 0) {
        int o = 0, t128 = 0, t32 = 0;
        for (int e = 0; e < NE; e++) {
            g_off[e] = o; g_tile128[e] = t128; g_tile32[e] = t32;
            int c = g_counts[e];
            o += c; t128 += (c + 127) >> 7; t32 += (c + 31) >> 5;
        }
        g_off[NE] = o; g_tile128[NE] = t128; g_tile32[NE] = t32;
    }
}

// ---------------- scatter ----------------
__global__ __launch_bounds__(256)
void scatter_kernel()
{
    const int b    = blockIdx.x * 256 + threadIdx.x;
    const int lane = threadIdx.x & 31;
#pragma unroll
    for (int s = 0; s < 2; s++) {
        int   e = g_tidx[b*2 + s];
        float w = g_tw[b*2 + s];
#pragma unroll
        for (int ee = 0; ee < NE; ee++) {
            unsigned m = __ballot_sync(0xffffffffu, e == ee);
            if (e == ee) {
                int rank   = __popc(m & ((1u << lane) - 1u));
                int leader = __ffs(m) - 1;
                int base = 0;
                if (lane == leader) base = atomicAdd(&g_cursor[ee], __popc(m));
                base = __shfl_sync(m, base, leader);
                int p = g_off[ee] + base + rank;
                g_tok[p] = b; g_wt[p] = w;
            }
        }
    }
}

// ---------------- layer 4 (K=256, N=32) + weighted combine ----------------
__global__ __launch_bounds__(256)
void l4_combine_kernel(const float* __restrict__ W4, const float* __restrict__ B4,
                       float* __restrict__ out)
{
    const int bx = blockIdx.x;
    if (bx >= g_tile32[NE]) return;
    int e = 0;
    while (bx >= g_tile32[e+1]) e++;
    const int row0   = g_off[e] + (bx - g_tile32[e]) * 32;
    const int rowEnd = g_off[e+1];

    __shared__ float sW[E3*NA];
    const float* We = W4 + (size_t)e * E3 * NA;
    for (int i = threadIdx.x; i < E3*NA/4; i += 256)
        *(float4*)&sW[i*4] = *(const float4*)&We[i*4];
    __syncthreads();

    const int r  = threadIdx.x >> 3;
    const int c4 = (threadIdx.x & 7) * 4;
    const int row = row0 + r;
    if (row >= rowEnd) return;

    const __half2* hh = (const __half2*)(g_h3 + (size_t)row * E3);
    float a0 = 0.f, a1 = 0.f, a2 = 0.f, a3 = 0.f;
#pragma unroll 4
    for (int k = 0; k < E3; k += 4) {
        float2 p0 = __half22float2(hh[k/2]);
        float2 p1 = __half22float2(hh[k/2+1]);
        float4 w0 = *(float4*)&sW[(k+0)*NA + c4];
        float4 w1 = *(float4*)&sW[(k+1)*NA + c4];
        float4 w2 = *(float4*)&sW[(k+2)*NA + c4];
        float4 w3 = *(float4*)&sW[(k+3)*NA + c4];
        a0 += p0.x*w0.x + p0.y*w1.x + p1.x*w2.x + p1.y*w3.x;
        a1 += p0.x*w0.y + p0.y*w1.y + p1.x*w2.y + p1.y*w3.y;
        a2 += p0.x*w0.z + p0.y*w1.z + p1.x*w2.z + p1.y*w3.z;
        a3 += p0.x*w0.w + p0.y*w1.w + p1.x*w2.w + p1.y*w3.w;
    }
    const int   tok = g_tok[row];
    const float w   = g_wt[row];
    float* o = out + (size_t)tok * NA + c4;
    atomicAdd(o+0, w*(a0 + B4[e*NA + c4 + 0]));
    atomicAdd(o+1, w*(a1 + B4[e*NA + c4 + 1]));
    atomicAdd(o+2, w*(a2 + B4[e*NA + c4 + 2]));
    atomicAdd(o+3, w*(a3 + B4[e*NA + c4 + 3]));
}

// ---------------- launch ----------------
static inline void split_launch(const float* x, h16* hi, h16* lo, size_t n) {
    int n4 = (int)(n / 4);
    split_kernel<<<(n4 + 255)/256, 256>>>((const float4*)x, (__half2*)hi, (__half2*)lo, n4);
}

#define SMEM3 (3 * (2*A_BYTES + 2*B_BYTES))   // 113664 (ASPLIT=1)
#define SMEM2 (3 * (A_BYTES + 2*B_BYTES))     //  82944 (ASPLIT=0)

extern "C" void kernel_launch(void* const* d_in, const int* in_sizes, int n_in,
                              void* d_out, int out_size)
{
    const float* obs = (const float*)d_in[0];
    const float* gw1 = (const float*)d_in[1];
    const float* gb1 = (const float*)d_in[2];
    const float* gw2 = (const float*)d_in[3];
    const float* gb2 = (const float*)d_in[4];
    const float* gw3 = (const float*)d_in[5];
    const float* gb3 = (const float*)d_in[6];
    const float* ew1 = (const float*)d_in[7];
    const float* eb1 = (const float*)d_in[8];
    const float* ew2 = (const float*)d_in[9];
    const float* eb2 = (const float*)d_in[10];
    const float* ew3 = (const float*)d_in[11];
    const float* eb3 = (const float*)d_in[12];
    const float* ew4 = (const float*)d_in[13];
    const float* eb4 = (const float*)d_in[14];
    float* out = (float*)d_out;

    h16 *obs_h, *obs_l, *gw1h, *gw1l, *gw2h, *gw2l;
    h16 *ew1h, *ew1l, *ew2h, *ew2l, *ew3h, *ew3l;
    h16 *g1h, *g1l, *h1, *h2, *h3;
    float *pg2;
    cudaGetSymbolAddress((void**)&obs_h, g_obs_h); cudaGetSymbolAddress((void**)&obs_l, g_obs_l);
    cudaGetSymbolAddress((void**)&gw1h, g_gw1h);   cudaGetSymbolAddress((void**)&gw1l, g_gw1l);
    cudaGetSymbolAddress((void**)&gw2h, g_gw2h);   cudaGetSymbolAddress((void**)&gw2l, g_gw2l);
    cudaGetSymbolAddress((void**)&ew1h, g_ew1h);   cudaGetSymbolAddress((void**)&ew1l, g_ew1l);
    cudaGetSymbolAddress((void**)&ew2h, g_ew2h);   cudaGetSymbolAddress((void**)&ew2l, g_ew2l);
    cudaGetSymbolAddress((void**)&ew3h, g_ew3h);   cudaGetSymbolAddress((void**)&ew3l, g_ew3l);
    cudaGetSymbolAddress((void**)&g1h, g_g1h);     cudaGetSymbolAddress((void**)&g1l, g_g1l);
    cudaGetSymbolAddress((void**)&h1, g_h1);
    cudaGetSymbolAddress((void**)&h2, g_h2);
    cudaGetSymbolAddress((void**)&h3, g_h3);
    cudaGetSymbolAddress((void**)&pg2, g_g2);

    cudaFuncSetAttribute(mma_gemm<false,false,true ,1>, cudaFuncAttributeMaxDynamicSharedMemorySize, SMEM3);
    cudaFuncSetAttribute(mma_gemm<false,false,true ,2>, cudaFuncAttributeMaxDynamicSharedMemorySize, SMEM3);
    cudaFuncSetAttribute(mma_gemm<true ,true ,false,0>, cudaFuncAttributeMaxDynamicSharedMemorySize, SMEM2);
    cudaFuncSetAttribute(mma_gemm<true ,false,false,0>, cudaFuncAttributeMaxDynamicSharedMemorySize, SMEM2);

    init_kernel<<<1, 32>>>();
    cudaMemsetAsync(out, 0, (size_t)out_size * sizeof(float));

    // operand prep (hi/lo splits; obs lo needed only for exact gating)
    split_launch(obs, obs_h, obs_l, (size_t)BB*DOBS);
    split_launch(gw1, gw1h, gw1l, (size_t)DOBS*G1);
    split_launch(gw2, gw2h, gw2l, (size_t)G1*G2);
    split_launch(ew1, ew1h, ew1l, (size_t)NE*DOBS*E1);
    split_launch(ew2, ew2h, ew2l, (size_t)NE*E1*E2);
    split_launch(ew3, ew3h, ew3l, (size_t)NE*E2*E3);

    // gating MLP: 3-pass (exact -> no top-k flips)
    mma_gemm<false,false,true ,1><<<dim3(BB/128, G1/128), 256, SMEM3>>>(
        obs_h, obs_l, gw1h, gw1l, gb1, g1h, g1l, nullptr, BB, DOBS, G1);
    mma_gemm<false,false,true ,2><<<dim3(BB/128, G2/128), 256, SMEM3>>>(
        g1h, g1l, gw2h, gw2l, gb2, nullptr, nullptr, pg2, BB, G1, G2);
    gate_topk_kernel<<<BB/64, 128>>>(gw3, gb3);
    offsets_kernel<<<1, 32>>>();
    scatter_kernel<<<BB/256, 256>>>();

    // grouped expert layers: 2-pass W-split (A single fp16)
    const int T128 = NP/128 + NE;   // 264
    const int T32  = NP/32  + NE;   // 1032
    mma_gemm<true,true ,false,0><<<dim3(T128, E1/128), 256, SMEM2>>>(
        obs_h, nullptr, ew1h, ew1l, eb1, h1, nullptr, nullptr, 0, DOBS, E1);
    mma_gemm<true,false,false,0><<<dim3(T128, E2/128), 256, SMEM2>>>(
        h1, nullptr, ew2h, ew2l, eb2, h2, nullptr, nullptr, 0, E1, E2);
    mma_gemm<true,false,false,0><<<dim3(T128, E3/128), 256, SMEM2>>>(
        h2, nullptr, ew3h, ew3l, eb3, h3, nullptr, nullptr, 0, E2, E3);

    // layer 4 + weighted combine
    l4_combine_kernel<<<T32, 256>>>(ew4, eb4, out);
}

// round 8
// speedup vs baseline: 4.6551x; 1.2993x over previous
#include <cuda_runtime.h>
#include <cuda_fp16.h>
#include <cstdint>

#define BB   16384
#define DOBS 512
#define NE   8
#define NA   32
#define G1   256
#define G2   128
#define E1   1024
#define E2   512
#define E3   256
#define NP   (2*BB)

typedef __half h16;

// ---------------- scratch ----------------
__device__ __align__(16) h16 g_obs_h[BB*DOBS], g_obs_l[BB*DOBS];
// gating weights: fp16 hi/lo; expert weights: single fp16 ([K,N] per expert)
__device__ __align__(16) h16 g_gw1h[DOBS*G1], g_gw1l[DOBS*G1];
__device__ __align__(16) h16 g_gw2h[G1*G2],   g_gw2l[G1*G2];
__device__ __align__(16) h16 g_ew1h[NE*DOBS*E1];
__device__ __align__(16) h16 g_ew2h[NE*E1*E2];
__device__ __align__(16) h16 g_ew3h[NE*E2*E3];

__device__ __align__(16) h16 g_g1h[BB*G1], g_g1l[BB*G1];
__device__ __align__(16) float g_g2[BB*G2];
// expert activations: single fp16
__device__ __align__(16) h16 g_h1[(size_t)NP*E1];
__device__ __align__(16) h16 g_h2[(size_t)NP*E2];
__device__ __align__(16) h16 g_h3[(size_t)NP*E3];

__device__ int   g_tidx[BB*2];
__device__ float g_tw[BB*2];
__device__ int   g_counts[NE];
__device__ int   g_off[NE+1];
__device__ int   g_tile128[NE+1];
__device__ int   g_tile32[NE+1];
__device__ int   g_cursor[NE];
__device__ int   g_tok[NP];
__device__ float g_wt[NP];

__device__ __forceinline__ float eluf(float x) { return x > 0.f ? x : expm1f(x); }

// ---------------- PTX helpers ----------------
__device__ __forceinline__ void mma_f16(float* c, const unsigned* a, const unsigned* b) {
    asm volatile(
        "mma.sync.aligned.m16n8k16.row.col.f32.f16.f16.f32 "
        "{%0,%1,%2,%3}, {%4,%5,%6,%7}, {%8,%9}, {%0,%1,%2,%3};"
        : "+f"(c[0]), "+f"(c[1]), "+f"(c[2]), "+f"(c[3])
        : "r"(a[0]), "r"(a[1]), "r"(a[2]), "r"(a[3]), "r"(b[0]), "r"(b[1]));
}
__device__ __forceinline__ void ldsm_x4(unsigned* r, unsigned addr) {
    asm volatile("ldmatrix.sync.aligned.m8n8.x4.shared.b16 {%0,%1,%2,%3}, [%4];"
                 : "=r"(r[0]), "=r"(r[1]), "=r"(r[2]), "=r"(r[3]) : "r"(addr));
}
__device__ __forceinline__ void ldsm_x4_t(unsigned* r, unsigned addr) {
    asm volatile("ldmatrix.sync.aligned.m8n8.x4.trans.shared.b16 {%0,%1,%2,%3}, [%4];"
                 : "=r"(r[0]), "=r"(r[1]), "=r"(r[2]), "=r"(r[3]) : "r"(addr));
}
__device__ __forceinline__ uint32_t s2u(const void* p) {
    uint32_t a;
    asm("{ .reg .u64 t; cvta.to.shared.u64 t, %1; cvt.u32.u64 %0, t; }" : "=r"(a) : "l"(p));
    return a;
}
__device__ __forceinline__ void cpa16(uint32_t dst, const void* src, uint32_t sz) {
    asm volatile("cp.async.cg.shared.global [%0], [%1], 16, %2;" :: "r"(dst), "l"(src), "r"(sz) : "memory");
}
__device__ __forceinline__ void cpcommit() { asm volatile("cp.async.commit_group;" ::: "memory"); }
template<int N> __device__ __forceinline__ void cpwait() { asm volatile("cp.async.wait_group %0;" :: "n"(N) : "memory"); }

// ---------------- split fp32 -> (hi, lo) fp16 ----------------
__global__ __launch_bounds__(256)
void split_kernel(const float4* __restrict__ x, __half2* __restrict__ hi,
                  __half2* __restrict__ lo, int n4)
{
    int i = blockIdx.x * 256 + threadIdx.x;
    if (i >= n4) return;
    float4 v = x[i];
    h16 h0 = __float2half_rn(v.x), h1 = __float2half_rn(v.y);
    h16 h2 = __float2half_rn(v.z), h3 = __float2half_rn(v.w);
    hi[2*i]   = __halves2half2(h0, h1);
    hi[2*i+1] = __halves2half2(h2, h3);
    if (lo) {
        lo[2*i]   = __halves2half2(__float2half_rn(v.x - __half2float(h0)),
                                   __float2half_rn(v.y - __half2float(h1)));
        lo[2*i+1] = __halves2half2(__float2half_rn(v.z - __half2float(h2)),
                                   __float2half_rn(v.w - __half2float(h3)));
    }
}

// ---------------- init ----------------
__global__ void init_kernel() {
    int t = threadIdx.x;
    if (t < NE) { g_counts[t] = 0; g_cursor[t] = 0; }
}

// ---------------- pipelined fp16 TC grouped GEMM ----------------
// NPASS==3 (gating): C = Ah@Bh + Ah@Bl + Al@Bh  (exact to ~1e-7)
// NPASS==1 (experts): C = A@Bh                   (plain fp16)
// CTA tile 128x128, BK=32, 3-stage cp.async, 256 threads.
// OUTM: 0 = fp16 single, 1 = fp16 hi/lo, 2 = fp32
#define A_BYTES 10240   // 128 x 40 halves
#define B_BYTES 8704    // 32 x 136 halves

template<bool GROUPED, bool GATHER, int NPASS, int OUTM>
__global__ __launch_bounds__(256)
void mma_gemm(const h16* __restrict__ Ah, const h16* __restrict__ Al,
              const h16* __restrict__ Wh, const h16* __restrict__ Wl,
              const float* __restrict__ bias,
              h16* __restrict__ Ch, h16* __restrict__ Cl, float* __restrict__ Cf,
              int M, int K, int N)
{
    constexpr bool TRI = (NPASS == 3);
    constexpr uint32_t AL_OFF = A_BYTES;
    constexpr uint32_t BH_OFF = TRI ? 2*A_BYTES : A_BYTES;
    constexpr uint32_t BL_OFF = BH_OFF + B_BYTES;
    constexpr uint32_t STG    = BH_OFF + (TRI ? 2 : 1) * B_BYTES;

    extern __shared__ __align__(128) char sm[];
    int row0, rowEnd;
    if (GROUPED) {
        int bx = blockIdx.x;
        if (bx >= g_tile128[NE]) return;
        int e = 0;
        while (bx >= g_tile128[e+1]) e++;
        row0   = g_off[e] + (bx - g_tile128[e]) * 128;
        rowEnd = g_off[e+1];
        if (row0 >= rowEnd) return;
        Wh   += (size_t)e * K * N;
        if (TRI) Wl += (size_t)e * K * N;
        bias += e * N;
    } else {
        row0   = blockIdx.x * 128;
        rowEnd = M;
    }
    const int n0  = blockIdx.y * 128;
    const int tid = threadIdx.x, lane = tid & 31, wid = tid >> 5;
    const int warpM = wid & 3, warpN = wid >> 2;
    const uint32_t su = s2u(sm);

    // A load mapping: 2 rows/thread (r, r+64), chunk ach of 4x16B per 64B row
    const int ar  = tid >> 2;
    const int ach = tid & 3;
    const h16 *pAh[2], *pAl[2];
    uint32_t asz[2];
#pragma unroll
    for (int i = 0; i < 2; i++) {
        int gr = row0 + ar + 64*i;
        bool v = gr < rowEnd;
        asz[i] = v ? 16u : 0u;
        size_t rowIdx = 0;
        if (v) rowIdx = GATHER ? (size_t)g_tok[gr] : (size_t)gr;
        pAh[i] = Ah + rowIdx * K + ach*8;
        if (TRI) pAl[i] = Al + rowIdx * K + ach*8;
    }
    // B load mapping: 2 k-rows/thread (k, k+16), chunk of 16x16B per 256B row
    const int br  = tid >> 4;
    const int bch = tid & 15;
    const h16* pBh = Wh + (size_t)br * N + n0 + bch*8;
    const h16* pBl = TRI ? (Wl + (size_t)br * N + n0 + bch*8) : nullptr;

    float acc[2][8][4];
#pragma unroll
    for (int mt = 0; mt < 2; mt++)
#pragma unroll
        for (int nt = 0; nt < 8; nt++)
#pragma unroll
            for (int q = 0; q < 4; q++) acc[mt][nt][q] = 0.f;

    const int S = K >> 5;

    auto LOAD = [&](int t) {
        uint32_t base = su + (uint32_t)(t % 3) * STG;
        int kf = t * 32;
#pragma unroll
        for (int i = 0; i < 2; i++) {
            uint32_t d = base + (uint32_t)((ar + 64*i)*80 + ach*16);
            cpa16(d, pAh[i] + kf, asz[i]);
            if (TRI) cpa16(d + AL_OFF, pAl[i] + kf, asz[i]);
        }
#pragma unroll
        for (int i = 0; i < 2; i++) {
            uint32_t d = base + (uint32_t)((br + 16*i)*272 + bch*16);
            cpa16(d + BH_OFF, pBh + (size_t)(kf + 16*i) * N, 16u);
            if (TRI) cpa16(d + BL_OFF, pBl + (size_t)(kf + 16*i) * N, 16u);
        }
        cpcommit();
    };

    LOAD(0);
    LOAD(1);

    for (int s = 0; s < S; s++) {
        __syncthreads();               // all warps done with buffer (s+2)%3
        int rem = S - 1 - s;
        if (rem >= 2) { LOAD(s+2); cpwait<2>(); }
        else if (rem == 1) cpwait<1>();
        else cpwait<0>();
        __syncthreads();               // stage s visible

        const uint32_t aBase = su + (uint32_t)(s % 3) * STG;
#pragma unroll
        for (int kk = 0; kk < 32; kk += 16) {
            unsigned ah[2][4], al[2][4];
#pragma unroll
            for (int mt = 0; mt < 2; mt++) {
                uint32_t off = (uint32_t)(((warpM*32 + mt*16 + (lane & 15))*40 + kk + 8*(lane >> 4)) * 2);
                ldsm_x4(ah[mt], aBase + off);
                if (TRI) ldsm_x4(al[mt], aBase + AL_OFF + off);
            }
            const int brow = kk + (lane & 15);
#pragma unroll
            for (int np = 0; np < 4; np++) {
                const int bcol = warpN*64 + np*16 + 8*(lane >> 4);
                uint32_t boff = (uint32_t)((brow*136 + bcol) * 2);
                unsigned bh[4], bl[4];
                ldsm_x4_t(bh, aBase + BH_OFF + boff);
                if (TRI) ldsm_x4_t(bl, aBase + BL_OFF + boff);
#pragma unroll
                for (int mt = 0; mt < 2; mt++) {
                    mma_f16(acc[mt][2*np],   ah[mt], bh);
                    mma_f16(acc[mt][2*np+1], ah[mt], bh+2);
                    if (TRI) {
                        mma_f16(acc[mt][2*np],   ah[mt], bl);
                        mma_f16(acc[mt][2*np+1], ah[mt], bl+2);
                        mma_f16(acc[mt][2*np],   al[mt], bh);
                        mma_f16(acc[mt][2*np+1], al[mt], bh+2);
                    }
                }
            }
        }
    }

    // ---------------- epilogue ----------------
#pragma unroll
    for (int mt = 0; mt < 2; mt++) {
        int r0 = row0 + warpM*32 + mt*16 + (lane >> 2);
#pragma unroll
        for (int nt = 0; nt < 8; nt++) {
            int c = n0 + warpN*64 + nt*8 + 2*(lane & 3);
            float b0 = __ldg(bias + c), b1 = __ldg(bias + c + 1);
            float v00 = eluf(acc[mt][nt][0] + b0);
            float v01 = eluf(acc[mt][nt][1] + b1);
            float v10 = eluf(acc[mt][nt][2] + b0);
            float v11 = eluf(acc[mt][nt][3] + b1);
#pragma unroll
            for (int rr = 0; rr < 2; rr++) {
                int r = r0 + rr*8;
                float va = rr ? v10 : v00, vb = rr ? v11 : v01;
                if (r < rowEnd) {
                    if (OUTM == 0) {
                        *(__half2*)(Ch + (size_t)r*N + c) =
                            __halves2half2(__float2half_rn(va), __float2half_rn(vb));
                    } else if (OUTM == 1) {
                        h16 h0 = __float2half_rn(va), h1 = __float2half_rn(vb);
                        *(__half2*)(Ch + (size_t)r*N + c) = __halves2half2(h0, h1);
                        *(__half2*)(Cl + (size_t)r*N + c) =
                            __halves2half2(__float2half_rn(va - __half2float(h0)),
                                           __float2half_rn(vb - __half2float(h1)));
                    } else {
                        *(float2*)(Cf + (size_t)r*N + c) = make_float2(va, vb);
                    }
                }
            }
        }
    }
}

// ---------------- gating head: logits + top-2 + renorm + counts ----------------
__global__ __launch_bounds__(128)
void gate_topk_kernel(const float* __restrict__ gw3, const float* __restrict__ gb3)
{
    __shared__ float sG[64*129];
    __shared__ float sW[G2*NE];
    __shared__ float sB[NE];
    const int tid = threadIdx.x;
    const int b0  = blockIdx.x * 64;
    for (int i = tid; i < 64*G2; i += 128)
        sG[(i >> 7)*129 + (i & 127)] = g_g2[(size_t)b0*G2 + i];
    for (int i = tid; i < G2*NE; i += 128) sW[i] = gw3[i];
    if (tid < NE) sB[tid] = gb3[tid];
    __syncthreads();
    if (tid < 64) {
        float lg[NE];
#pragma unroll
        for (int j = 0; j < NE; j++) lg[j] = sB[j];
        for (int k = 0; k < G2; k++) {
            float gv = sG[tid*129 + k];
#pragma unroll
            for (int j = 0; j < NE; j++) lg[j] += gv * sW[k*NE + j];
        }
        int i0 = 0; float m0 = lg[0];
#pragma unroll
        for (int j = 1; j < NE; j++) if (lg[j] > m0) { m0 = lg[j]; i0 = j; }
        int i1 = -1; float m1 = -3.4e38f;
#pragma unroll
        for (int j = 0; j < NE; j++) if (j != i0 && lg[j] > m1) { m1 = lg[j]; i1 = j; }
        float e1  = expf(m1 - m0);
        float inv = 1.f / (1.f + e1);
        int b = b0 + tid;
        g_tidx[b*2+0] = i0; g_tidx[b*2+1] = i1;
        g_tw[b*2+0] = inv;  g_tw[b*2+1] = e1 * inv;
        atomicAdd(&g_counts[i0], 1);
        atomicAdd(&g_counts[i1], 1);
    }
}

// ---------------- prefix sums ----------------
__global__ void offsets_kernel()
{
    if (threadIdx.x == 0 && blockIdx.x == 0) {
        int o = 0, t128 = 0, t32 = 0;
        for (int e = 0; e < NE; e++) {
            g_off[e] = o; g_tile128[e] = t128; g_tile32[e] = t32;
            int c = g_counts[e];
            o += c; t128 += (c + 127) >> 7; t32 += (c + 31) >> 5;
        }
        g_off[NE] = o; g_tile128[NE] = t128; g_tile32[NE] = t32;
    }
}

// ---------------- scatter ----------------
__global__ __launch_bounds__(256)
void scatter_kernel()
{
    const int b    = blockIdx.x * 256 + threadIdx.x;
    const int lane = threadIdx.x & 31;
#pragma unroll
    for (int s = 0; s < 2; s++) {
        int   e = g_tidx[b*2 + s];
        float w = g_tw[b*2 + s];
#pragma unroll
        for (int ee = 0; ee < NE; ee++) {
            unsigned m = __ballot_sync(0xffffffffu, e == ee);
            if (e == ee) {
                int rank   = __popc(m & ((1u << lane) - 1u));
                int leader = __ffs(m) - 1;
                int base = 0;
                if (lane == leader) base = atomicAdd(&g_cursor[ee], __popc(m));
                base = __shfl_sync(m, base, leader);
                int p = g_off[ee] + base + rank;
                g_tok[p] = b; g_wt[p] = w;
            }
        }
    }
}

// ---------------- layer 4 (K=256, N=32) + weighted combine ----------------
__global__ __launch_bounds__(256)
void l4_combine_kernel(const float* __restrict__ W4, const float* __restrict__ B4,
                       float* __restrict__ out)
{
    const int bx = blockIdx.x;
    if (bx >= g_tile32[NE]) return;
    int e = 0;
    while (bx >= g_tile32[e+1]) e++;
    const int row0   = g_off[e] + (bx - g_tile32[e]) * 32;
    const int rowEnd = g_off[e+1];

    __shared__ float sW[E3*NA];
    const float* We = W4 + (size_t)e * E3 * NA;
    for (int i = threadIdx.x; i < E3*NA/4; i += 256)
        *(float4*)&sW[i*4] = *(const float4*)&We[i*4];
    __syncthreads();

    const int r  = threadIdx.x >> 3;
    const int c4 = (threadIdx.x & 7) * 4;
    const int row = row0 + r;
    if (row >= rowEnd) return;

    const __half2* hh = (const __half2*)(g_h3 + (size_t)row * E3);
    float a0 = 0.f, a1 = 0.f, a2 = 0.f, a3 = 0.f;
#pragma unroll 4
    for (int k = 0; k < E3; k += 4) {
        float2 p0 = __half22float2(hh[k/2]);
        float2 p1 = __half22float2(hh[k/2+1]);
        float4 w0 = *(float4*)&sW[(k+0)*NA + c4];
        float4 w1 = *(float4*)&sW[(k+1)*NA + c4];
        float4 w2 = *(float4*)&sW[(k+2)*NA + c4];
        float4 w3 = *(float4*)&sW[(k+3)*NA + c4];
        a0 += p0.x*w0.x + p0.y*w1.x + p1.x*w2.x + p1.y*w3.x;
        a1 += p0.x*w0.y + p0.y*w1.y + p1.x*w2.y + p1.y*w3.y;
        a2 += p0.x*w0.z + p0.y*w1.z + p1.x*w2.z + p1.y*w3.z;
        a3 += p0.x*w0.w + p0.y*w1.w + p1.x*w2.w + p1.y*w3.w;
    }
    const int   tok = g_tok[row];
    const float w   = g_wt[row];
    float* o = out + (size_t)tok * NA + c4;
    atomicAdd(o+0, w*(a0 + B4[e*NA + c4 + 0]));
    atomicAdd(o+1, w*(a1 + B4[e*NA + c4 + 1]));
    atomicAdd(o+2, w*(a2 + B4[e*NA + c4 + 2]));
    atomicAdd(o+3, w*(a3 + B4[e*NA + c4 + 3]));
}

// ---------------- launch ----------------
static inline void split_launch(const float* x, h16* hi, h16* lo, size_t n) {
    int n4 = (int)(n / 4);
    split_kernel<<<(n4 + 255)/256, 256>>>((const float4*)x, (__half2*)hi, (__half2*)lo, n4);
}

#define SMEM3 (3 * (2*A_BYTES + 2*B_BYTES))   // 113664 (gating)
#define SMEM1 (3 * (A_BYTES + B_BYTES))       //  56832 (experts)

extern "C" void kernel_launch(void* const* d_in, const int* in_sizes, int n_in,
                              void* d_out, int out_size)
{
    const float* obs = (const float*)d_in[0];
    const float* gw1 = (const float*)d_in[1];
    const float* gb1 = (const float*)d_in[2];
    const float* gw2 = (const float*)d_in[3];
    const float* gb2 = (const float*)d_in[4];
    const float* gw3 = (const float*)d_in[5];
    const float* gb3 = (const float*)d_in[6];
    const float* ew1 = (const float*)d_in[7];
    const float* eb1 = (const float*)d_in[8];
    const float* ew2 = (const float*)d_in[9];
    const float* eb2 = (const float*)d_in[10];
    const float* ew3 = (const float*)d_in[11];
    const float* eb3 = (const float*)d_in[12];
    const float* ew4 = (const float*)d_in[13];
    const float* eb4 = (const float*)d_in[14];
    float* out = (float*)d_out;

    h16 *obs_h, *obs_l, *gw1h, *gw1l, *gw2h, *gw2l;
    h16 *ew1h, *ew2h, *ew3h;
    h16 *g1h, *g1l, *h1, *h2, *h3;
    float *pg2;
    cudaGetSymbolAddress((void**)&obs_h, g_obs_h); cudaGetSymbolAddress((void**)&obs_l, g_obs_l);
    cudaGetSymbolAddress((void**)&gw1h, g_gw1h);   cudaGetSymbolAddress((void**)&gw1l, g_gw1l);
    cudaGetSymbolAddress((void**)&gw2h, g_gw2h);   cudaGetSymbolAddress((void**)&gw2l, g_gw2l);
    cudaGetSymbolAddress((void**)&ew1h, g_ew1h);
    cudaGetSymbolAddress((void**)&ew2h, g_ew2h);
    cudaGetSymbolAddress((void**)&ew3h, g_ew3h);
    cudaGetSymbolAddress((void**)&g1h, g_g1h);     cudaGetSymbolAddress((void**)&g1l, g_g1l);
    cudaGetSymbolAddress((void**)&h1, g_h1);
    cudaGetSymbolAddress((void**)&h2, g_h2);
    cudaGetSymbolAddress((void**)&h3, g_h3);
    cudaGetSymbolAddress((void**)&pg2, g_g2);

    cudaFuncSetAttribute(mma_gemm<false,false,3,1>, cudaFuncAttributeMaxDynamicSharedMemorySize, SMEM3);
    cudaFuncSetAttribute(mma_gemm<false,false,3,2>, cudaFuncAttributeMaxDynamicSharedMemorySize, SMEM3);
    cudaFuncSetAttribute(mma_gemm<true ,true ,1,0>, cudaFuncAttributeMaxDynamicSharedMemorySize, SMEM1);
    cudaFuncSetAttribute(mma_gemm<true ,false,1,0>, cudaFuncAttributeMaxDynamicSharedMemorySize, SMEM1);

    init_kernel<<<1, 32>>>();
    cudaMemsetAsync(out, 0, (size_t)out_size * sizeof(float));

    // operand prep
    split_launch(obs, obs_h, obs_l, (size_t)BB*DOBS);
    split_launch(gw1, gw1h, gw1l, (size_t)DOBS*G1);
    split_launch(gw2, gw2h, gw2l, (size_t)G1*G2);
    split_launch(ew1, ew1h, nullptr, (size_t)NE*DOBS*E1);
    split_launch(ew2, ew2h, nullptr, (size_t)NE*E1*E2);
    split_launch(ew3, ew3h, nullptr, (size_t)NE*E2*E3);

    // gating MLP: 3-pass (exact -> no top-k flips)
    mma_gemm<false,false,3,1><<<dim3(BB/128, G1/128), 256, SMEM3>>>(
        obs_h, obs_l, gw1h, gw1l, gb1, g1h, g1l, nullptr, BB, DOBS, G1);
    mma_gemm<false,false,3,2><<<dim3(BB/128, G2/128), 256, SMEM3>>>(
        g1h, g1l, gw2h, gw2l, gb2, nullptr, nullptr, pg2, BB, G1, G2);
    gate_topk_kernel<<<BB/64, 128>>>(gw3, gb3);
    offsets_kernel<<<1, 32>>>();
    scatter_kernel<<<BB/256, 256>>>();

    // grouped expert layers: single-pass fp16
    const int T128 = NP/128 + NE;   // 264
    const int T32  = NP/32  + NE;   // 1032
    mma_gemm<true,true ,1,0><<<dim3(T128, E1/128), 256, SMEM1>>>(
        obs_h, nullptr, ew1h, nullptr, eb1, h1, nullptr, nullptr, 0, DOBS, E1);
    mma_gemm<true,false,1,0><<<dim3(T128, E2/128), 256, SMEM1>>>(
        h1, nullptr, ew2h, nullptr, eb2, h2, nullptr, nullptr, 0, E1, E2);
    mma_gemm<true,false,1,0><<<dim3(T128, E3/128), 256, SMEM1>>>(
        h2, nullptr, ew3h, nullptr, eb3, h3, nullptr, nullptr, 0, E2, E3);

    // layer 4 + weighted combine
    l4_combine_kernel<<<T32, 256>>>(ew4, eb4, out);
}